// round 2
// baseline (speedup 1.0000x reference)
#include <cuda_runtime.h>

#define B_ 8
#define L_ 1024
#define D_ 512
#define H_ 8
#define DK_ 64
#define M_ (B_*L_)

// Scratch (no allocations allowed)
__device__ float g_Q[B_*H_*L_*DK_];
__device__ float g_K[B_*H_*L_*DK_];
__device__ float g_V[B_*H_*L_*DK_];
__device__ float g_X[B_*L_*D_];

// ---------------------------------------------------------------------------
// C = A (M x 512) * W^T (512 x 512, W row-major N x K) + bias
// HEADS=1: write C in (B, H, L, DK) head-split layout; HEADS=0: row-major MxN.
// 64x64 block tile, 32 k-tile, 256 threads, 4x4 per thread.
// ---------------------------------------------------------------------------
template<int HEADS>
__global__ __launch_bounds__(256) void gemm_nt_kernel(
    const float* __restrict__ A, const float* __restrict__ W,
    const float* __restrict__ bias, float* __restrict__ C)
{
    __shared__ float As[32][68];
    __shared__ float Bs[32][68];
    const int tid = threadIdx.x;
    const int tx = tid & 15, ty = tid >> 4;
    const int m0 = blockIdx.y * 64, n0 = blockIdx.x * 64;

    float acc[4][4] = {};

#pragma unroll 1
    for (int kt = 0; kt < D_ / 32; ++kt) {
        __syncthreads();
#pragma unroll
        for (int p = 0; p < 2; ++p) {
            int e = (tid + p * 256) * 4;           // 0..2047
            int m = e >> 5, k = e & 31;
            float4 a4 = *(const float4*)&A[(size_t)(m0 + m) * D_ + kt * 32 + k];
            As[k + 0][m] = a4.x; As[k + 1][m] = a4.y;
            As[k + 2][m] = a4.z; As[k + 3][m] = a4.w;
            float4 b4 = *(const float4*)&W[(size_t)(n0 + m) * D_ + kt * 32 + k];
            Bs[k + 0][m] = b4.x; Bs[k + 1][m] = b4.y;
            Bs[k + 2][m] = b4.z; Bs[k + 3][m] = b4.w;
        }
        __syncthreads();
#pragma unroll
        for (int k = 0; k < 32; ++k) {
            float4 a = *(const float4*)&As[k][ty * 4];
            float4 b = *(const float4*)&Bs[k][tx * 4];
            acc[0][0] += a.x * b.x; acc[0][1] += a.x * b.y; acc[0][2] += a.x * b.z; acc[0][3] += a.x * b.w;
            acc[1][0] += a.y * b.x; acc[1][1] += a.y * b.y; acc[1][2] += a.y * b.z; acc[1][3] += a.y * b.w;
            acc[2][0] += a.z * b.x; acc[2][1] += a.z * b.y; acc[2][2] += a.z * b.z; acc[2][3] += a.z * b.w;
            acc[3][0] += a.w * b.x; acc[3][1] += a.w * b.y; acc[3][2] += a.w * b.z; acc[3][3] += a.w * b.w;
        }
    }

    const int nb = n0 + tx * 4;
    float4 bv = *(const float4*)&bias[nb];
#pragma unroll
    for (int ii = 0; ii < 4; ++ii) {
        int m = m0 + ty * 4 + ii;
        float4 r;
        r.x = acc[ii][0] + bv.x; r.y = acc[ii][1] + bv.y;
        r.z = acc[ii][2] + bv.z; r.w = acc[ii][3] + bv.w;
        if (HEADS) {
            int b = m >> 10, l = m & (L_ - 1);
            int h = nb >> 6, dk = nb & 63;
            *(float4*)&C[((size_t)(b * H_ + h) * L_ + l) * DK_ + dk] = r;
        } else {
            *(float4*)&C[(size_t)m * D_ + nb] = r;
        }
    }
}

// ---------------------------------------------------------------------------
// Flash-style attention with per-head distance bias.
// Block: one (b,h) x 64 query rows. TK=32 key tile, online softmax.
// ---------------------------------------------------------------------------
__global__ __launch_bounds__(256) void attn_kernel(
    const float* __restrict__ Q, const float* __restrict__ K,
    const float* __restrict__ V, const float* __restrict__ dist,
    const unsigned char* __restrict__ mask,
    const float* __restrict__ logwb, float* __restrict__ X)
{
    __shared__ float Qs[64][68];   // [d][i] transposed Q tile
    __shared__ float Ks[64][36];   // [d][j] transposed K tile
    __shared__ float Ss[32][68];   // [j][i] distance tile, then P tile
    __shared__ float Vs[32][68];   // [j][d] V tile
    __shared__ float red[16][64];  // reduction partials
    __shared__ float m_s[64], l_s[64], sc_s[64];

    const int tid = threadIdx.x;
    const int tx = tid & 15, ty = tid >> 4;
    const int bh = blockIdx.y;
    const int b = bh >> 3, h = bh & 7;
    const int q0 = blockIdx.x * 64;
    const float wb = __expf(logwb[h]);

    // Load Q tile transposed
    const float* Qb = Q + (size_t)(bh * L_ + q0) * DK_;
#pragma unroll
    for (int p = 0; p < 4; ++p) {
        int e = (tid + p * 256) * 4;   // 0..4095
        int i = e >> 6, d = e & 63;
        float4 v4 = *(const float4*)&Qb[i * DK_ + d];
        Qs[d + 0][i] = v4.x; Qs[d + 1][i] = v4.y;
        Qs[d + 2][i] = v4.z; Qs[d + 3][i] = v4.w;
    }
    if (tid < 64) { m_s[tid] = -1e30f; l_s[tid] = 0.f; }

    float o[4][4] = {};

    const float* Kb = K + (size_t)bh * L_ * DK_;
    const float* Vb = V + (size_t)bh * L_ * DK_;

    for (int k0 = 0; k0 < L_; k0 += 32) {
        __syncthreads();
        // Load K (transposed), V (natural)
#pragma unroll
        for (int p = 0; p < 2; ++p) {
            int e = (tid + p * 256) * 4;   // 0..2047
            int j = e >> 6, d = e & 63;
            float4 kv = *(const float4*)&Kb[(k0 + j) * DK_ + d];
            Ks[d + 0][j] = kv.x; Ks[d + 1][j] = kv.y;
            Ks[d + 2][j] = kv.z; Ks[d + 3][j] = kv.w;
            float4 vv = *(const float4*)&Vb[(k0 + j) * DK_ + d];
            *(float4*)&Vs[j][d] = vv;
        }
        // Distance/mask tile -> Ss[j][i] (coalesced along k)
#pragma unroll
        for (int p = 0; p < 2; ++p) {
            int e = (tid + p * 256) * 4;
            int i = e >> 5, j = e & 31;
            size_t base = (size_t)(b * L_ + q0 + i) * L_ + k0 + j;
            float4 dv = *(const float4*)&dist[base];
            uchar4 mv = *(const uchar4*)&mask[base];
            if (mv.x) dv.x = 1e30f;
            if (mv.y) dv.y = 1e30f;
            if (mv.z) dv.z = 1e30f;
            if (mv.w) dv.w = 1e30f;
            Ss[j + 0][i] = dv.x; Ss[j + 1][i] = dv.y;
            Ss[j + 2][i] = dv.z; Ss[j + 3][i] = dv.w;
        }
        __syncthreads();

        // S^T micro-tile: rows j = ty*2+{0,1}, cols i = tx*4+{0..3}
        const int j0 = ty * 2, i0 = tx * 4;
        float s0[4] = {}, s1[4] = {};
#pragma unroll
        for (int d = 0; d < 64; ++d) {
            float ka = Ks[d][j0], kb = Ks[d][j0 + 1];
            float4 q4 = *(const float4*)&Qs[d][i0];
            s0[0] += ka * q4.x; s0[1] += ka * q4.y; s0[2] += ka * q4.z; s0[3] += ka * q4.w;
            s1[0] += kb * q4.x; s1[1] += kb * q4.y; s1[2] += kb * q4.z; s1[3] += kb * q4.w;
        }
#pragma unroll
        for (int ii = 0; ii < 4; ++ii) {
            s0[ii] = s0[ii] * 0.125f - Ss[j0][i0 + ii] * wb;
            s1[ii] = s1[ii] * 0.125f - Ss[j0 + 1][i0 + ii] * wb;
        }
        __syncthreads();   // all dist reads done; red buffer free

        // Partial row max
#pragma unroll
        for (int ii = 0; ii < 4; ++ii)
            red[ty][i0 + ii] = fmaxf(s0[ii], s1[ii]);
        __syncthreads();
        if (tid < 64) {
            float mx = red[0][tid];
#pragma unroll
            for (int r = 1; r < 16; ++r) mx = fmaxf(mx, red[r][tid]);
            float mo = m_s[tid];
            float mn = fmaxf(mo, mx);
            sc_s[tid] = __expf(mo - mn);
            m_s[tid] = mn;
        }
        __syncthreads();

        // P = exp(S - m), write back to Ss, partial sums
#pragma unroll
        for (int ii = 0; ii < 4; ++ii) {
            float mm = m_s[i0 + ii];
            float p0 = __expf(s0[ii] - mm);
            float p1 = __expf(s1[ii] - mm);
            Ss[j0][i0 + ii] = p0;
            Ss[j0 + 1][i0 + ii] = p1;
            red[ty][i0 + ii] = p0 + p1;
        }
        __syncthreads();
        if (tid < 64) {
            float rs = 0.f;
#pragma unroll
            for (int r = 0; r < 16; ++r) rs += red[r][tid];
            l_s[tid] = l_s[tid] * sc_s[tid] + rs;
        }

        // O accumulate: rows i = ty*4+ii, cols d = tx*4+dd
        const int pi0 = ty * 4, pd0 = tx * 4;
#pragma unroll
        for (int ii = 0; ii < 4; ++ii) {
            float sc = sc_s[pi0 + ii];
            o[ii][0] *= sc; o[ii][1] *= sc; o[ii][2] *= sc; o[ii][3] *= sc;
        }
#pragma unroll
        for (int j = 0; j < 32; ++j) {
            float4 pp = *(const float4*)&Ss[j][pi0];
            float4 vv = *(const float4*)&Vs[j][pd0];
            o[0][0] += pp.x * vv.x; o[0][1] += pp.x * vv.y; o[0][2] += pp.x * vv.z; o[0][3] += pp.x * vv.w;
            o[1][0] += pp.y * vv.x; o[1][1] += pp.y * vv.y; o[1][2] += pp.y * vv.z; o[1][3] += pp.y * vv.w;
            o[2][0] += pp.z * vv.x; o[2][1] += pp.z * vv.y; o[2][2] += pp.z * vv.z; o[2][3] += pp.z * vv.w;
            o[3][0] += pp.w * vv.x; o[3][1] += pp.w * vv.y; o[3][2] += pp.w * vv.z; o[3][3] += pp.w * vv.w;
        }
    }
    __syncthreads();

    // Normalize and write X in (B, L, D) layout
#pragma unroll
    for (int ii = 0; ii < 4; ++ii) {
        int i = ty * 4 + ii;
        float inv = 1.f / l_s[i];
        float4 r;
        r.x = o[ii][0] * inv; r.y = o[ii][1] * inv;
        r.z = o[ii][2] * inv; r.w = o[ii][3] * inv;
        *(float4*)&X[(size_t)(b * L_ + q0 + i) * D_ + h * DK_ + tx * 4] = r;
    }
}

// ---------------------------------------------------------------------------
extern "C" void kernel_launch(void* const* d_in, const int* in_sizes, int n_in,
                              void* d_out, int out_size)
{
    const float* query = (const float*)d_in[0];
    const float* key_  = (const float*)d_in[1];
    const float* value = (const float*)d_in[2];
    const float* dist  = (const float*)d_in[3];
    const unsigned char* mask = (const unsigned char*)d_in[4];
    const float* Wq = (const float*)d_in[5];
    const float* bq = (const float*)d_in[6];
    const float* Wk = (const float*)d_in[7];
    const float* bk = (const float*)d_in[8];
    const float* Wv = (const float*)d_in[9];
    const float* bv = (const float*)d_in[10];
    const float* Wo = (const float*)d_in[11];
    const float* bo = (const float*)d_in[12];
    const float* logwb = (const float*)d_in[13];

    float *Qp, *Kp, *Vp, *Xp;
    cudaGetSymbolAddress((void**)&Qp, g_Q);
    cudaGetSymbolAddress((void**)&Kp, g_K);
    cudaGetSymbolAddress((void**)&Vp, g_V);
    cudaGetSymbolAddress((void**)&Xp, g_X);

    dim3 ggrid(D_ / 64, M_ / 64);   // (8, 128)
    gemm_nt_kernel<1><<<ggrid, 256>>>(query, Wq, bq, Qp);
    gemm_nt_kernel<1><<<ggrid, 256>>>(key_,  Wk, bk, Kp);
    gemm_nt_kernel<1><<<ggrid, 256>>>(value, Wv, bv, Vp);

    dim3 agrid(L_ / 64, B_ * H_);   // (16, 64)
    attn_kernel<<<agrid, 256>>>(Qp, Kp, Vp, dist, mask, logwb, Xp);

    gemm_nt_kernel<0><<<ggrid, 256>>>(Xp, Wo, bo, (float*)d_out);
}

// round 3
// speedup vs baseline: 2.5170x; 2.5170x over previous
#include <cuda_runtime.h>
#include <cstdint>

#define B_ 8
#define L_ 1024
#define D_ 512
#define H_ 8
#define DK_ 64
#define M_ (B_*L_)

// Scratch (no allocations allowed)
__device__ float g_Q[B_*H_*L_*DK_];
__device__ float g_K[B_*H_*L_*DK_];
__device__ float g_V[B_*H_*L_*DK_];
__device__ float g_X[B_*L_*D_];

__device__ __forceinline__ uint32_t f2tf(float f) {
    uint32_t u;
    asm("cvt.rna.tf32.f32 %0, %1;" : "=r"(u) : "f"(f));
    return u;
}

__device__ __forceinline__ void mma_tf32(float* c, const uint32_t* a, const uint32_t* b) {
    asm volatile(
        "mma.sync.aligned.m16n8k8.row.col.f32.tf32.tf32.f32 "
        "{%0,%1,%2,%3}, {%4,%5,%6,%7}, {%8,%9}, {%0,%1,%2,%3};"
        : "+f"(c[0]), "+f"(c[1]), "+f"(c[2]), "+f"(c[3])
        : "r"(a[0]), "r"(a[1]), "r"(a[2]), "r"(a[3]), "r"(b[0]), "r"(b[1]));
}

// ---------------------------------------------------------------------------
// C = A (M x 512) * W^T + bias via tf32 mma.sync.
// Block tile 128m x 64n, k-tile 32, 8 warps (4 x 2).
// HEADS=1: write C in (B, H, L, DK) head-split layout; else row-major MxN.
// ---------------------------------------------------------------------------
template<int HEADS>
__global__ __launch_bounds__(256) void gemm_mma_kernel(
    const float* __restrict__ A, const float* __restrict__ W,
    const float* __restrict__ bias, float* __restrict__ C)
{
    __shared__ uint32_t As[128][36];
    __shared__ uint32_t Ws[64][36];

    const int tid = threadIdx.x;
    const int lane = tid & 31, warp = tid >> 5;
    const int wm = warp >> 1, wn = warp & 1;      // 4 x 2 warp grid
    const int g = lane >> 2, t = lane & 3;
    const int m0 = blockIdx.y * 128, n0 = blockIdx.x * 64;

    float acc[2][4][4] = {};                      // [mtile][ntile][reg]

#pragma unroll 1
    for (int kt = 0; kt < D_; kt += 32) {
        __syncthreads();
#pragma unroll
        for (int p = 0; p < 4; ++p) {             // A: 128x32
            int e = (tid + p * 256) * 4;
            int m = e >> 5, k = e & 31;
            float4 v = *(const float4*)&A[(size_t)(m0 + m) * D_ + kt + k];
            As[m][k] = f2tf(v.x); As[m][k + 1] = f2tf(v.y);
            As[m][k + 2] = f2tf(v.z); As[m][k + 3] = f2tf(v.w);
        }
#pragma unroll
        for (int p = 0; p < 2; ++p) {             // W: 64x32
            int e = (tid + p * 256) * 4;
            int n = e >> 5, k = e & 31;
            float4 v = *(const float4*)&W[(size_t)(n0 + n) * D_ + kt + k];
            Ws[n][k] = f2tf(v.x); Ws[n][k + 1] = f2tf(v.y);
            Ws[n][k + 2] = f2tf(v.z); Ws[n][k + 3] = f2tf(v.w);
        }
        __syncthreads();

#pragma unroll
        for (int kk = 0; kk < 4; ++kk) {
            const int kb = kk * 8;
            uint32_t a[2][4], b[4][2];
#pragma unroll
            for (int mt = 0; mt < 2; ++mt) {
                int r = wm * 32 + mt * 16;
                a[mt][0] = As[r + g][kb + t];
                a[mt][1] = As[r + g + 8][kb + t];
                a[mt][2] = As[r + g][kb + t + 4];
                a[mt][3] = As[r + g + 8][kb + t + 4];
            }
#pragma unroll
            for (int nt = 0; nt < 4; ++nt) {
                int c = wn * 32 + nt * 8 + g;
                b[nt][0] = Ws[c][kb + t];
                b[nt][1] = Ws[c][kb + t + 4];
            }
#pragma unroll
            for (int mt = 0; mt < 2; ++mt)
#pragma unroll
                for (int nt = 0; nt < 4; ++nt)
                    mma_tf32(acc[mt][nt], a[mt], b[nt]);
        }
    }

    // Epilogue
#pragma unroll
    for (int mt = 0; mt < 2; ++mt) {
#pragma unroll
        for (int nt = 0; nt < 4; ++nt) {
            int n = n0 + wn * 32 + nt * 8 + 2 * t;
            float2 bv = *(const float2*)&bias[n];
            float2 r0, r1;
            r0.x = acc[mt][nt][0] + bv.x; r0.y = acc[mt][nt][1] + bv.y;
            r1.x = acc[mt][nt][2] + bv.x; r1.y = acc[mt][nt][3] + bv.y;
            int m_a = m0 + wm * 32 + mt * 16 + g;
            int m_b = m_a + 8;
            if (HEADS) {
                int h = n >> 6, dk = n & 63;
                int ba = m_a >> 10, la = m_a & (L_ - 1);
                int bb = m_b >> 10, lb = m_b & (L_ - 1);
                *(float2*)&C[((size_t)(ba * H_ + h) * L_ + la) * DK_ + dk] = r0;
                *(float2*)&C[((size_t)(bb * H_ + h) * L_ + lb) * DK_ + dk] = r1;
            } else {
                *(float2*)&C[(size_t)m_a * D_ + n] = r0;
                *(float2*)&C[(size_t)m_b * D_ + n] = r1;
            }
        }
    }
}

// ---------------------------------------------------------------------------
// Flash attention with per-head distance bias, tf32 mma.sync for QK^T and PV.
// One CTA per (b,h) x 64 query rows; k-tile = 64 keys; 8 warps (4m x 2n).
// P-tile aliases K-tile smem (dead after QK^T).
// ---------------------------------------------------------------------------
__global__ __launch_bounds__(256) void attn_mma_kernel(
    const float* __restrict__ Q, const float* __restrict__ K,
    const float* __restrict__ V, const float* __restrict__ dist,
    const unsigned char* __restrict__ mask,
    const float* __restrict__ logwb, float* __restrict__ X)
{
    __shared__ uint32_t KPs[64][68];   // K tile [key][dk], then P tile [q][key]
    __shared__ uint32_t Vs[64][72];    // V tile [key][d]
    __shared__ float redm[2][64], reds[2][64];

    const int tid = threadIdx.x;
    const int lane = tid & 31, warp = tid >> 5;
    const int wm = warp >> 1, wn = warp & 1;   // 4 x 2
    const int g = lane >> 2, t = lane & 3;
    const int bh = blockIdx.y;
    const int b = bh >> 3, h = bh & 7;
    const int q0 = blockIdx.x * 64;
    const float wb = __expf(logwb[h]);
    const int qr = wm * 16;                    // warp's q-row base (local)

    // Stage Q tile through KPs, pull A-fragments into registers (kept whole loop)
    const float* Qb = Q + (size_t)(bh * L_ + q0) * DK_;
#pragma unroll
    for (int p = 0; p < 4; ++p) {
        int e = (tid + p * 256) * 4;
        int i = e >> 6, d = e & 63;
        float4 v = *(const float4*)&Qb[i * DK_ + d];
        KPs[i][d] = f2tf(v.x); KPs[i][d + 1] = f2tf(v.y);
        KPs[i][d + 2] = f2tf(v.z); KPs[i][d + 3] = f2tf(v.w);
    }
    __syncthreads();
    uint32_t qa[8][4];
#pragma unroll
    for (int kk = 0; kk < 8; ++kk) {
        int kb = kk * 8;
        qa[kk][0] = KPs[qr + g][kb + t];
        qa[kk][1] = KPs[qr + g + 8][kb + t];
        qa[kk][2] = KPs[qr + g][kb + t + 4];
        qa[kk][3] = KPs[qr + g + 8][kb + t + 4];
    }

    float o[4][4] = {};
    float mrow[2] = {-1e30f, -1e30f};
    float lrow[2] = {0.f, 0.f};

    const float* Kb = K + (size_t)bh * L_ * DK_;
    const float* Vb = V + (size_t)bh * L_ * DK_;
    const float* dro0 = dist + ((size_t)(b * L_ + q0 + qr + g)) * L_;
    const float* dro1 = dro0 + 8 * L_;
    const unsigned char* mro0 = mask + ((size_t)(b * L_ + q0 + qr + g)) * L_;
    const unsigned char* mro1 = mro0 + 8 * L_;

#pragma unroll 1
    for (int k0 = 0; k0 < L_; k0 += 64) {
        __syncthreads();   // previous PV done with KPs/Vs
        // Load K, V tiles (64 x 64 each), converted to tf32
#pragma unroll
        for (int p = 0; p < 4; ++p) {
            int e = (tid + p * 256) * 4;
            int j = e >> 6, d = e & 63;
            float4 kv = *(const float4*)&Kb[(k0 + j) * DK_ + d];
            KPs[j][d] = f2tf(kv.x); KPs[j][d + 1] = f2tf(kv.y);
            KPs[j][d + 2] = f2tf(kv.z); KPs[j][d + 3] = f2tf(kv.w);
            float4 vv = *(const float4*)&Vb[(k0 + j) * DK_ + d];
            Vs[j][d] = f2tf(vv.x); Vs[j][d + 1] = f2tf(vv.y);
            Vs[j][d + 2] = f2tf(vv.z); Vs[j][d + 3] = f2tf(vv.w);
        }
        __syncthreads();

        // S = Q K^T (warp covers 16 q-rows x 32 key-cols)
        float s[4][4] = {};
#pragma unroll
        for (int kk = 0; kk < 8; ++kk) {
            int kb = kk * 8;
            uint32_t bfr[4][2];
#pragma unroll
            for (int nt = 0; nt < 4; ++nt) {
                int c = wn * 32 + nt * 8 + g;
                bfr[nt][0] = KPs[c][kb + t];
                bfr[nt][1] = KPs[c][kb + t + 4];
            }
#pragma unroll
            for (int nt = 0; nt < 4; ++nt)
                mma_tf32(s[nt], qa[kk], bfr[nt]);
        }

        // scale + distance bias + mask
        const int cb = k0 + wn * 32 + 2 * t;
#pragma unroll
        for (int nt = 0; nt < 4; ++nt) {
            int c = cb + nt * 8;
            float2 d0 = *(const float2*)&dro0[c];
            float2 d1 = *(const float2*)&dro1[c];
            uchar2 m0v = *(const uchar2*)&mro0[c];
            uchar2 m1v = *(const uchar2*)&mro1[c];
            s[nt][0] = m0v.x ? -1e9f : s[nt][0] * 0.125f - d0.x * wb;
            s[nt][1] = m0v.y ? -1e9f : s[nt][1] * 0.125f - d0.y * wb;
            s[nt][2] = m1v.x ? -1e9f : s[nt][2] * 0.125f - d1.x * wb;
            s[nt][3] = m1v.y ? -1e9f : s[nt][3] * 0.125f - d1.y * wb;
        }

        // row max (thread -> 4-lane shfl -> cross-warp_n via smem)
        float tm0 = -1e30f, tm1 = -1e30f;
#pragma unroll
        for (int nt = 0; nt < 4; ++nt) {
            tm0 = fmaxf(tm0, fmaxf(s[nt][0], s[nt][1]));
            tm1 = fmaxf(tm1, fmaxf(s[nt][2], s[nt][3]));
        }
        tm0 = fmaxf(tm0, __shfl_xor_sync(0xffffffff, tm0, 1));
        tm0 = fmaxf(tm0, __shfl_xor_sync(0xffffffff, tm0, 2));
        tm1 = fmaxf(tm1, __shfl_xor_sync(0xffffffff, tm1, 1));
        tm1 = fmaxf(tm1, __shfl_xor_sync(0xffffffff, tm1, 2));
        if (t == 0) {
            redm[wn][qr + g] = tm0;
            redm[wn][qr + g + 8] = tm1;
        }
        __syncthreads();   // also: all QK^T reads of KPs complete

        float mn0 = fmaxf(mrow[0], fmaxf(redm[0][qr + g], redm[1][qr + g]));
        float mn1 = fmaxf(mrow[1], fmaxf(redm[0][qr + g + 8], redm[1][qr + g + 8]));
        float sc0 = __expf(mrow[0] - mn0);
        float sc1 = __expf(mrow[1] - mn1);
        mrow[0] = mn0; mrow[1] = mn1;

        // P = exp(S - m), write tf32 into KPs (now P tile), partial row sums
        float sum0 = 0.f, sum1 = 0.f;
#pragma unroll
        for (int nt = 0; nt < 4; ++nt) {
            int c = wn * 32 + nt * 8 + 2 * t;
            float p00 = __expf(s[nt][0] - mn0);
            float p01 = __expf(s[nt][1] - mn0);
            float p10 = __expf(s[nt][2] - mn1);
            float p11 = __expf(s[nt][3] - mn1);
            KPs[qr + g][c] = f2tf(p00);     KPs[qr + g][c + 1] = f2tf(p01);
            KPs[qr + g + 8][c] = f2tf(p10); KPs[qr + g + 8][c + 1] = f2tf(p11);
            sum0 += p00 + p01;
            sum1 += p10 + p11;
        }
        sum0 += __shfl_xor_sync(0xffffffff, sum0, 1);
        sum0 += __shfl_xor_sync(0xffffffff, sum0, 2);
        sum1 += __shfl_xor_sync(0xffffffff, sum1, 1);
        sum1 += __shfl_xor_sync(0xffffffff, sum1, 2);
        if (t == 0) {
            reds[wn][qr + g] = sum0;
            reds[wn][qr + g + 8] = sum1;
        }

        // rescale O accumulators
#pragma unroll
        for (int nt = 0; nt < 4; ++nt) {
            o[nt][0] *= sc0; o[nt][1] *= sc0;
            o[nt][2] *= sc1; o[nt][3] *= sc1;
        }
        __syncthreads();   // P tile + reds visible

        lrow[0] = lrow[0] * sc0 + reds[0][qr + g] + reds[1][qr + g];
        lrow[1] = lrow[1] * sc1 + reds[0][qr + g + 8] + reds[1][qr + g + 8];

        // O += P V  (warp: 16 q-rows x 32 d-cols)
#pragma unroll
        for (int kk = 0; kk < 8; ++kk) {
            int kb = kk * 8;
            uint32_t pa[4];
            pa[0] = KPs[qr + g][kb + t];
            pa[1] = KPs[qr + g + 8][kb + t];
            pa[2] = KPs[qr + g][kb + t + 4];
            pa[3] = KPs[qr + g + 8][kb + t + 4];
            uint32_t bfr[4][2];
#pragma unroll
            for (int nt = 0; nt < 4; ++nt) {
                int c = wn * 32 + nt * 8 + g;
                bfr[nt][0] = Vs[kb + t][c];
                bfr[nt][1] = Vs[kb + t + 4][c];
            }
#pragma unroll
            for (int nt = 0; nt < 4; ++nt)
                mma_tf32(o[nt], pa, bfr[nt]);
        }
    }

    // Normalize, write X in (B, L, D)
    float inv0 = 1.f / lrow[0];
    float inv1 = 1.f / lrow[1];
    const size_t xr0 = (size_t)(b * L_ + q0 + qr + g) * D_ + h * DK_;
    const size_t xr1 = xr0 + 8 * D_;
#pragma unroll
    for (int nt = 0; nt < 4; ++nt) {
        int c = wn * 32 + nt * 8 + 2 * t;
        float2 r0, r1;
        r0.x = o[nt][0] * inv0; r0.y = o[nt][1] * inv0;
        r1.x = o[nt][2] * inv1; r1.y = o[nt][3] * inv1;
        *(float2*)&X[xr0 + c] = r0;
        *(float2*)&X[xr1 + c] = r1;
    }
}

// ---------------------------------------------------------------------------
extern "C" void kernel_launch(void* const* d_in, const int* in_sizes, int n_in,
                              void* d_out, int out_size)
{
    const float* query = (const float*)d_in[0];
    const float* key_  = (const float*)d_in[1];
    const float* value = (const float*)d_in[2];
    const float* dist  = (const float*)d_in[3];
    const unsigned char* mask = (const unsigned char*)d_in[4];
    const float* Wq = (const float*)d_in[5];
    const float* bq = (const float*)d_in[6];
    const float* Wk = (const float*)d_in[7];
    const float* bk = (const float*)d_in[8];
    const float* Wv = (const float*)d_in[9];
    const float* bv = (const float*)d_in[10];
    const float* Wo = (const float*)d_in[11];
    const float* bo = (const float*)d_in[12];
    const float* logwb = (const float*)d_in[13];

    float *Qp, *Kp, *Vp, *Xp;
    cudaGetSymbolAddress((void**)&Qp, g_Q);
    cudaGetSymbolAddress((void**)&Kp, g_K);
    cudaGetSymbolAddress((void**)&Vp, g_V);
    cudaGetSymbolAddress((void**)&Xp, g_X);

    dim3 ggrid(D_ / 64, M_ / 128);   // (8, 64)
    gemm_mma_kernel<1><<<ggrid, 256>>>(query, Wq, bq, Qp);
    gemm_mma_kernel<1><<<ggrid, 256>>>(key_,  Wk, bk, Kp);
    gemm_mma_kernel<1><<<ggrid, 256>>>(value, Wv, bv, Vp);

    dim3 agrid(L_ / 64, B_ * H_);    // (16, 64)
    attn_mma_kernel<<<agrid, 256>>>(Qp, Kp, Vp, dist, mask, logwb, Xp);

    gemm_mma_kernel<0><<<ggrid, 256>>>(Xp, Wo, bo, (float*)d_out);
}

// round 6
// speedup vs baseline: 3.1441x; 1.2492x over previous
#include <cuda_runtime.h>
#include <cstdint>

#define B_ 8
#define L_ 1024
#define D_ 512
#define H_ 8
#define DK_ 64
#define M_ (B_*L_)

// Scratch (no allocations allowed)
__device__ float g_Q[B_*H_*L_*DK_];
__device__ float g_K[B_*H_*L_*DK_];
__device__ float g_V[B_*H_*L_*DK_];
__device__ float g_X[B_*L_*D_];

// ---------------------------------------------------------------------------
// helpers
// ---------------------------------------------------------------------------
__device__ __forceinline__ uint32_t smem_to_u32(const void* p) {
    uint32_t a;
    asm("{ .reg .u64 t; cvta.to.shared.u64 t, %1; cvt.u32.u64 %0, t; }"
        : "=r"(a) : "l"(p));
    return a;
}
__device__ __forceinline__ void cp16(uint32_t dst, const void* src) {
    asm volatile("cp.async.cg.shared.global [%0], [%1], 16;"
                 :: "r"(dst), "l"(src));
}
#define CP_COMMIT asm volatile("cp.async.commit_group;")
#define CP_WAIT(n) asm volatile("cp.async.wait_group %0;" :: "n"(n))

// round f32 -> tf32 (RNA), result as bit pattern
__device__ __forceinline__ uint32_t f2tf(float f) {
    uint32_t u;
    asm("cvt.rna.tf32.f32 %0, %1;" : "=r"(u) : "f"(f));
    return u;
}

// mma.sync tf32 m16n8k8
__device__ __forceinline__ void mma_tf32(float* c, const uint32_t* a, const uint32_t* b) {
    asm volatile(
        "mma.sync.aligned.m16n8k8.row.col.f32.tf32.tf32.f32 "
        "{%0,%1,%2,%3}, {%4,%5,%6,%7}, {%8,%9}, {%0,%1,%2,%3};"
        : "+f"(c[0]), "+f"(c[1]), "+f"(c[2]), "+f"(c[3])
        : "r"(a[0]), "r"(a[1]), "r"(a[2]), "r"(a[3]), "r"(b[0]), "r"(b[1]));
}

// ===========================================================================
// Fused projection GEMM: C_z = A_z (8192 x 512) * W_z^T + bias_z
// Tile 128m x 64n x 32k, 3-stage cp.async pipeline, 8 warps (4m x 2n).
// Fragments RNA-rounded to tf32 after LDS. heads=1: head-split output layout
// with outputs rounded to tf32-valued floats (so attention mma is exact).
// ===========================================================================
#define GBM 128
#define GBN 64
#define GBK 32
#define GKT (D_ / GBK)              // 16
#define GA(s) ((s) * 16384)         // A buf: 128 rows x 128B
#define GB(s) (49152 + (s) * 8192)  // B buf: 64 rows x 128B
#define GSM 73728

__global__ __launch_bounds__(256) void gemm3_kernel(
    const float* __restrict__ A0, const float* __restrict__ A1, const float* __restrict__ A2,
    const float* __restrict__ W0, const float* __restrict__ W1, const float* __restrict__ W2,
    const float* __restrict__ bp0, const float* __restrict__ bp1, const float* __restrict__ bp2,
    float* __restrict__ C0, float* __restrict__ C1, float* __restrict__ C2,
    int heads)
{
    extern __shared__ char sm[];
    const uint32_t sb = smem_to_u32(sm);
    const int z = blockIdx.z;
    const float* A    = (z == 0) ? A0 : (z == 1) ? A1 : A2;
    const float* W    = (z == 0) ? W0 : (z == 1) ? W1 : W2;
    const float* bias = (z == 0) ? bp0 : (z == 1) ? bp1 : bp2;
    float* C          = (z == 0) ? C0 : (z == 1) ? C1 : C2;

    const int tid = threadIdx.x;
    const int lane = tid & 31, warp = tid >> 5;
    const int wm = warp >> 1, wn = warp & 1;
    const int g = lane >> 2, t = lane & 3;
    const int m0 = blockIdx.y * GBM, n0 = blockIdx.x * GBN;

    auto stage = [&](int kt, int s) {
        const float* Ab = A + (size_t)m0 * D_ + kt * GBK;
#pragma unroll
        for (int i = 0; i < 4; ++i) {          // A: 128 rows x 8 chunks
            int ci = tid + 256 * i;
            int row = ci >> 3, ch = ci & 7;
            cp16(sb + GA(s) + row * 128 + ((ch ^ (row & 7)) << 4),
                 Ab + (size_t)row * D_ + ch * 4);
        }
        const float* Wb = W + (size_t)n0 * D_ + kt * GBK;
#pragma unroll
        for (int i = 0; i < 2; ++i) {          // B: 64 rows x 8 chunks
            int ci = tid + 256 * i;
            int row = ci >> 3, ch = ci & 7;
            cp16(sb + GB(s) + row * 128 + ((ch ^ (row & 7)) << 4),
                 Wb + (size_t)row * D_ + ch * 4);
        }
        CP_COMMIT;
    };

    stage(0, 0);
    stage(1, 1);

    float acc[2][4][4] = {};

#pragma unroll 1
    for (int kt = 0; kt < GKT; ++kt) {
        if (kt < GKT - 1) { CP_WAIT(1); } else { CP_WAIT(0); }
        __syncthreads();
        if (kt + 2 < GKT) stage(kt + 2, (kt + 2) % 3);

        const uint32_t Ao = GA(kt % 3), Bo = GB(kt % 3);
#pragma unroll
        for (int kk = 0; kk < 4; ++kk) {
            uint32_t a[2][4], bf[4][2];
#pragma unroll
            for (int mt = 0; mt < 2; ++mt) {
                uint32_t r0 = Ao + (uint32_t)(wm * 32 + mt * 16 + g) * 128 + 4 * t;
                uint32_t r1 = r0 + 8 * 128;
                a[mt][0] = f2tf(*(const float*)(sm + r0 + (((2 * kk) ^ g) << 4)));
                a[mt][1] = f2tf(*(const float*)(sm + r1 + (((2 * kk) ^ g) << 4)));
                a[mt][2] = f2tf(*(const float*)(sm + r0 + (((2 * kk + 1) ^ g) << 4)));
                a[mt][3] = f2tf(*(const float*)(sm + r1 + (((2 * kk + 1) ^ g) << 4)));
            }
#pragma unroll
            for (int nt = 0; nt < 4; ++nt) {
                uint32_t rb = Bo + (uint32_t)(wn * 32 + nt * 8 + g) * 128 + 4 * t;
                bf[nt][0] = f2tf(*(const float*)(sm + rb + (((2 * kk) ^ g) << 4)));
                bf[nt][1] = f2tf(*(const float*)(sm + rb + (((2 * kk + 1) ^ g) << 4)));
            }
#pragma unroll
            for (int mt = 0; mt < 2; ++mt)
#pragma unroll
                for (int nt = 0; nt < 4; ++nt)
                    mma_tf32(acc[mt][nt], a[mt], bf[nt]);
        }
    }

    // Epilogue
#pragma unroll
    for (int mt = 0; mt < 2; ++mt) {
#pragma unroll
        for (int nt = 0; nt < 4; ++nt) {
            int n = n0 + wn * 32 + nt * 8 + 2 * t;
            float2 bv = *(const float2*)&bias[n];
            float2 r0, r1;
            r0.x = acc[mt][nt][0] + bv.x; r0.y = acc[mt][nt][1] + bv.y;
            r1.x = acc[mt][nt][2] + bv.x; r1.y = acc[mt][nt][3] + bv.y;
            int m_a = m0 + wm * 32 + mt * 16 + g;
            int m_b = m_a + 8;
            if (heads) {
                // round to tf32-valued floats so attention's mma is exact-RNA
                r0.x = __uint_as_float(f2tf(r0.x)); r0.y = __uint_as_float(f2tf(r0.y));
                r1.x = __uint_as_float(f2tf(r1.x)); r1.y = __uint_as_float(f2tf(r1.y));
                int h = n >> 6, dk = n & 63;
                int ba = m_a >> 10, la = m_a & (L_ - 1);
                int bb = m_b >> 10, lb = m_b & (L_ - 1);
                *(float2*)&C[((size_t)(ba * H_ + h) * L_ + la) * DK_ + dk] = r0;
                *(float2*)&C[((size_t)(bb * H_ + h) * L_ + lb) * DK_ + dk] = r1;
            } else {
                *(float2*)&C[(size_t)m_a * D_ + n] = r0;
                *(float2*)&C[(size_t)m_b * D_ + n] = r1;
            }
        }
    }
}

// ===========================================================================
// Flash attention, mma.sync tf32, cp.async double-buffered K/V staging.
// Q/K/V are pre-rounded to tf32 values by the projection epilogue, so the
// QK^T and PV mmas are exact (no cvt in the hot loop; P rounded at store).
// K layout: pitch 256B + 16B-chunk XOR swizzle. V: pitch 288B linear.
// ===========================================================================
#define AK(s) ((s) * 16384)                 // K bufs: 64 x 256B
#define AV(s) (32768 + (s) * 18432)         // V bufs: 64 x 288B
#define AP 69632                            // P: 64 x 272B (Q staged here first)
#define ARM 87040                           // redm: 2 x 64 floats
#define ARS 87552                           // reds: 2 x 64 floats
#define ASM 88064

__global__ __launch_bounds__(256) void attn_kernel(
    const float* __restrict__ Q, const float* __restrict__ K,
    const float* __restrict__ V, const float* __restrict__ dist,
    const unsigned char* __restrict__ mask,
    const float* __restrict__ logwb, float* __restrict__ X)
{
    extern __shared__ char sm[];
    const uint32_t sb = smem_to_u32(sm);
    float* redm = (float*)(sm + ARM);
    float* reds = (float*)(sm + ARS);

    const int tid = threadIdx.x;
    const int lane = tid & 31, warp = tid >> 5;
    const int wm = warp >> 1, wn = warp & 1;
    const int g = lane >> 2, t = lane & 3;
    const int bh = blockIdx.y;
    const int b = bh >> 3, h = bh & 7;
    const int q0 = blockIdx.x * 64;
    const float wb = __expf(logwb[h]);
    const int qr = wm * 16;

    const float* Qb = Q + (size_t)(bh * L_ + q0) * DK_;
    const float* Kb = K + (size_t)bh * L_ * DK_;
    const float* Vb = V + (size_t)bh * L_ * DK_;

    auto stageKV = [&](int tile, int buf) {
        const float* Kt = Kb + (size_t)tile * 64 * DK_;
        const float* Vt = Vb + (size_t)tile * 64 * DK_;
#pragma unroll
        for (int i = 0; i < 4; ++i) {
            int ci = tid + 256 * i;
            int row = ci >> 4, ch = ci & 15;
            cp16(sb + AK(buf) + row * 256 + ((ch ^ (row & 7)) << 4),
                 Kt + row * DK_ + ch * 4);
            cp16(sb + AV(buf) + row * 288 + (ch << 4),
                 Vt + row * DK_ + ch * 4);
        }
        CP_COMMIT;
    };

    // Stage Q (into P region, XOR layout), then K/V tiles 0 and 1.
    {
#pragma unroll
        for (int i = 0; i < 4; ++i) {
            int ci = tid + 256 * i;
            int row = ci >> 4, ch = ci & 15;
            cp16(sb + AP + row * 256 + ((ch ^ (row & 7)) << 4),
                 Qb + row * DK_ + ch * 4);
        }
        CP_COMMIT;
    }
    stageKV(0, 0);
    stageKV(1, 1);

    CP_WAIT(2);          // Q done (K0V0 / K1V1 may still fly)
    __syncthreads();

    // Q fragments (held in registers for the whole loop)
    uint32_t qa[8][4];
#pragma unroll
    for (int kk = 0; kk < 8; ++kk) {
        uint32_t r0 = AP + (uint32_t)(qr + g) * 256 + 4 * t;
        uint32_t r1 = r0 + 8 * 256;
        qa[kk][0] = *(const uint32_t*)(sm + r0 + (((2 * kk) ^ g) << 4));
        qa[kk][1] = *(const uint32_t*)(sm + r1 + (((2 * kk) ^ g) << 4));
        qa[kk][2] = *(const uint32_t*)(sm + r0 + (((2 * kk + 1) ^ g) << 4));
        qa[kk][3] = *(const uint32_t*)(sm + r1 + (((2 * kk + 1) ^ g) << 4));
    }

    float o[4][4] = {};
    float mrow0 = -1e30f, mrow1 = -1e30f;
    float lrow0 = 0.f, lrow1 = 0.f;

    const float* dro0 = dist + (size_t)(b * L_ + q0 + qr + g) * L_;
    const float* dro1 = dro0 + 8 * L_;
    const unsigned char* mro0 = mask + (size_t)(b * L_ + q0 + qr + g) * L_;
    const unsigned char* mro1 = mro0 + 8 * L_;

#pragma unroll 1
    for (int it = 0; it < 16; ++it) {
        const int k0 = it * 64;
        if (it < 15) { CP_WAIT(1); } else { CP_WAIT(0); }
        __syncthreads();                       // sync1: tile `it` staged
        const uint32_t Ko = AK(it & 1), Vo = AV(it & 1);

        // Prefetch dist/mask (overlaps with QK^T mma)
        const int cb = k0 + wn * 32 + 2 * t;
        float2 dv0[4], dv1[4]; uchar2 mv0[4], mv1[4];
#pragma unroll
        for (int nt = 0; nt < 4; ++nt) {
            int c = cb + nt * 8;
            dv0[nt] = *(const float2*)&dro0[c];
            dv1[nt] = *(const float2*)&dro1[c];
            mv0[nt] = *(const uchar2*)&mro0[c];
            mv1[nt] = *(const uchar2*)&mro1[c];
        }

        // S = Q K^T (warp: 16 q-rows x 32 key-cols)
        float s[4][4] = {};
#pragma unroll
        for (int kk = 0; kk < 8; ++kk) {
#pragma unroll
            for (int nt = 0; nt < 4; ++nt) {
                uint32_t base = Ko + (uint32_t)(wn * 32 + nt * 8 + g) * 256 + 4 * t;
                uint32_t bf[2];
                bf[0] = *(const uint32_t*)(sm + base + (((2 * kk) ^ g) << 4));
                bf[1] = *(const uint32_t*)(sm + base + (((2 * kk + 1) ^ g) << 4));
                mma_tf32(s[nt], qa[kk], bf);
            }
        }

        // scale + distance bias + mask
#pragma unroll
        for (int nt = 0; nt < 4; ++nt) {
            s[nt][0] = mv0[nt].x ? -1e9f : s[nt][0] * 0.125f - dv0[nt].x * wb;
            s[nt][1] = mv0[nt].y ? -1e9f : s[nt][1] * 0.125f - dv0[nt].y * wb;
            s[nt][2] = mv1[nt].x ? -1e9f : s[nt][2] * 0.125f - dv1[nt].x * wb;
            s[nt][3] = mv1[nt].y ? -1e9f : s[nt][3] * 0.125f - dv1[nt].y * wb;
        }

        // row max
        float tm0 = -1e30f, tm1 = -1e30f;
#pragma unroll
        for (int nt = 0; nt < 4; ++nt) {
            tm0 = fmaxf(tm0, fmaxf(s[nt][0], s[nt][1]));
            tm1 = fmaxf(tm1, fmaxf(s[nt][2], s[nt][3]));
        }
        tm0 = fmaxf(tm0, __shfl_xor_sync(0xffffffff, tm0, 1));
        tm0 = fmaxf(tm0, __shfl_xor_sync(0xffffffff, tm0, 2));
        tm1 = fmaxf(tm1, __shfl_xor_sync(0xffffffff, tm1, 1));
        tm1 = fmaxf(tm1, __shfl_xor_sync(0xffffffff, tm1, 2));
        if (t == 0) {
            redm[wn * 64 + qr + g] = tm0;
            redm[wn * 64 + qr + g + 8] = tm1;
        }
        __syncthreads();                       // sync2

        float mn0 = fmaxf(mrow0, fmaxf(redm[qr + g], redm[64 + qr + g]));
        float mn1 = fmaxf(mrow1, fmaxf(redm[qr + g + 8], redm[64 + qr + g + 8]));
        float sc0 = __expf(mrow0 - mn0);
        float sc1 = __expf(mrow1 - mn1);
        mrow0 = mn0; mrow1 = mn1;

        // P = exp(S - m) -> P tile (pitch 272B, tf32-rounded), partial sums
        const uint32_t prow0 = AP + (uint32_t)(qr + g) * 272;
        const uint32_t prow1 = prow0 + 8 * 272;
        float sum0 = 0.f, sum1 = 0.f;
#pragma unroll
        for (int nt = 0; nt < 4; ++nt) {
            int c = wn * 32 + nt * 8 + 2 * t;
            float p00 = __expf(s[nt][0] - mn0);
            float p01 = __expf(s[nt][1] - mn0);
            float p10 = __expf(s[nt][2] - mn1);
            float p11 = __expf(s[nt][3] - mn1);
            *(uint2*)(sm + prow0 + c * 4) = make_uint2(f2tf(p00), f2tf(p01));
            *(uint2*)(sm + prow1 + c * 4) = make_uint2(f2tf(p10), f2tf(p11));
            sum0 += p00 + p01;
            sum1 += p10 + p11;
        }
        sum0 += __shfl_xor_sync(0xffffffff, sum0, 1);
        sum0 += __shfl_xor_sync(0xffffffff, sum0, 2);
        sum1 += __shfl_xor_sync(0xffffffff, sum1, 1);
        sum1 += __shfl_xor_sync(0xffffffff, sum1, 2);
        if (t == 0) {
            reds[wn * 64 + qr + g] = sum0;
            reds[wn * 64 + qr + g + 8] = sum1;
        }

        // rescale O
#pragma unroll
        for (int nt = 0; nt < 4; ++nt) {
            o[nt][0] *= sc0; o[nt][1] *= sc0;
            o[nt][2] *= sc1; o[nt][3] *= sc1;
        }
        __syncthreads();                       // sync3: P + reds visible

        lrow0 = lrow0 * sc0 + reds[qr + g] + reds[64 + qr + g];
        lrow1 = lrow1 * sc1 + reds[qr + g + 8] + reds[64 + qr + g + 8];

        // O += P V (warp: 16 q-rows x 32 d-cols)
#pragma unroll
        for (int kk = 0; kk < 8; ++kk) {
            uint32_t pa[4];
            pa[0] = *(const uint32_t*)(sm + prow0 + (8 * kk + t) * 4);
            pa[1] = *(const uint32_t*)(sm + prow1 + (8 * kk + t) * 4);
            pa[2] = *(const uint32_t*)(sm + prow0 + (8 * kk + t + 4) * 4);
            pa[3] = *(const uint32_t*)(sm + prow1 + (8 * kk + t + 4) * 4);
#pragma unroll
            for (int nt = 0; nt < 4; ++nt) {
                uint32_t vb = Vo + (uint32_t)(8 * kk + t) * 288
                              + (uint32_t)(wn * 32 + nt * 8 + g) * 4;
                uint32_t bf[2];
                bf[0] = *(const uint32_t*)(sm + vb);
                bf[1] = *(const uint32_t*)(sm + vb + 4 * 288);
                mma_tf32(o[nt], pa, bf);
            }
        }
        __syncthreads();                       // sync4: all reads of buf (it&1) done

        if (it + 2 < 16) stageKV(it + 2, it & 1);
    }

    // Normalize, write X in (B, L, D)
    float inv0 = 1.f / lrow0;
    float inv1 = 1.f / lrow1;
    const size_t xr0 = (size_t)(b * L_ + q0 + qr + g) * D_ + h * DK_;
    const size_t xr1 = xr0 + 8 * D_;
#pragma unroll
    for (int nt = 0; nt < 4; ++nt) {
        int c = wn * 32 + nt * 8 + 2 * t;
        float2 r0, r1;
        r0.x = o[nt][0] * inv0; r0.y = o[nt][1] * inv0;
        r1.x = o[nt][2] * inv1; r1.y = o[nt][3] * inv1;
        *(float2*)&X[xr0 + c] = r0;
        *(float2*)&X[xr1 + c] = r1;
    }
}

// ---------------------------------------------------------------------------
extern "C" void kernel_launch(void* const* d_in, const int* in_sizes, int n_in,
                              void* d_out, int out_size)
{
    const float* query = (const float*)d_in[0];
    const float* key_  = (const float*)d_in[1];
    const float* value = (const float*)d_in[2];
    const float* dist  = (const float*)d_in[3];
    const unsigned char* mask = (const unsigned char*)d_in[4];
    const float* Wq = (const float*)d_in[5];
    const float* bq = (const float*)d_in[6];
    const float* Wk = (const float*)d_in[7];
    const float* bk = (const float*)d_in[8];
    const float* Wv = (const float*)d_in[9];
    const float* bv = (const float*)d_in[10];
    const float* Wo = (const float*)d_in[11];
    const float* bo = (const float*)d_in[12];
    const float* logwb = (const float*)d_in[13];

    float *Qp, *Kp, *Vp, *Xp;
    cudaGetSymbolAddress((void**)&Qp, g_Q);
    cudaGetSymbolAddress((void**)&Kp, g_K);
    cudaGetSymbolAddress((void**)&Vp, g_V);
    cudaGetSymbolAddress((void**)&Xp, g_X);

    cudaFuncSetAttribute(gemm3_kernel,
                         cudaFuncAttributeMaxDynamicSharedMemorySize, GSM);
    cudaFuncSetAttribute(attn_kernel,
                         cudaFuncAttributeMaxDynamicSharedMemorySize, ASM);

    // Fused Q/K/V projections (z selects input/weights/output)
    gemm3_kernel<<<dim3(D_ / GBN, M_ / GBM, 3), 256, GSM>>>(
        query, key_, value, Wq, Wk, Wv, bq, bk, bv, Qp, Kp, Vp, 1);

    attn_kernel<<<dim3(L_ / 64, B_ * H_), 256, ASM>>>(
        Qp, Kp, Vp, dist, mask, logwb, Xp);

    // Output projection
    gemm3_kernel<<<dim3(D_ / GBN, M_ / GBM, 1), 256, GSM>>>(
        Xp, Xp, Xp, Wo, Wo, Wo, bo, bo, bo,
        (float*)d_out, (float*)d_out, (float*)d_out, 0);
}

// round 7
// speedup vs baseline: 4.8117x; 1.5304x over previous
#include <cuda_runtime.h>
#include <cuda_fp16.h>
#include <cstdint>

#define B_ 8
#define L_ 1024
#define D_ 512
#define H_ 8
#define DK_ 64
#define M_ (B_*L_)

// Scratch (no allocations allowed)
__device__ __half g_Ah[3][M_*D_];   // fp16 query/key/value
__device__ __half g_Wh[4][D_*D_];   // fp16 Wq,Wk,Wv,Wo
__device__ __half g_Q[B_*H_*L_*DK_];
__device__ __half g_K[B_*H_*L_*DK_];
__device__ __half g_V[B_*H_*L_*DK_];
__device__ __half g_X[M_*D_];

// ---------------------------------------------------------------------------
// helpers
// ---------------------------------------------------------------------------
__device__ __forceinline__ uint32_t smem_to_u32(const void* p) {
    uint32_t a;
    asm("{ .reg .u64 t; cvta.to.shared.u64 t, %1; cvt.u32.u64 %0, t; }"
        : "=r"(a) : "l"(p));
    return a;
}
__device__ __forceinline__ void cp16(uint32_t dst, const void* src) {
    asm volatile("cp.async.cg.shared.global [%0], [%1], 16;"
                 :: "r"(dst), "l"(src));
}
#define CP_COMMIT asm volatile("cp.async.commit_group;")
#define CP_WAIT(n) asm volatile("cp.async.wait_group %0;" :: "n"(n))

__device__ __forceinline__ void ldsm4(uint32_t* r, uint32_t addr) {
    asm volatile("ldmatrix.sync.aligned.m8n8.x4.shared.b16 {%0,%1,%2,%3}, [%4];"
        : "=r"(r[0]), "=r"(r[1]), "=r"(r[2]), "=r"(r[3]) : "r"(addr));
}
__device__ __forceinline__ void ldsm4t(uint32_t* r, uint32_t addr) {
    asm volatile("ldmatrix.sync.aligned.m8n8.x4.trans.shared.b16 {%0,%1,%2,%3}, [%4];"
        : "=r"(r[0]), "=r"(r[1]), "=r"(r[2]), "=r"(r[3]) : "r"(addr));
}
__device__ __forceinline__ void mma_f16(float* c, const uint32_t* a, const uint32_t* b) {
    asm volatile(
        "mma.sync.aligned.m16n8k16.row.col.f32.f16.f16.f32 "
        "{%0,%1,%2,%3}, {%4,%5,%6,%7}, {%8,%9}, {%0,%1,%2,%3};"
        : "+f"(c[0]), "+f"(c[1]), "+f"(c[2]), "+f"(c[3])
        : "r"(a[0]), "r"(a[1]), "r"(a[2]), "r"(a[3]), "r"(b[0]), "r"(b[1]));
}
__device__ __forceinline__ uint32_t h2u(__half2 h) { return *(uint32_t*)&h; }

// ===========================================================================
// fp32 -> fp16 convert pass (8 elems/thread)
// ===========================================================================
__global__ void cvt_kernel(const float4* __restrict__ s0, const float4* __restrict__ s1,
                           const float4* __restrict__ s2, const float4* __restrict__ s3,
                           uint4* d0, uint4* d1, uint4* d2, uint4* d3)
{
    const int z = blockIdx.z;
    const float4* s = (z == 0) ? s0 : (z == 1) ? s1 : (z == 2) ? s2 : s3;
    uint4* d = (z == 0) ? d0 : (z == 1) ? d1 : (z == 2) ? d2 : d3;
    const int i = blockIdx.x * blockDim.x + threadIdx.x;
    float4 u = s[2 * i], v = s[2 * i + 1];
    uint4 o;
    o.x = h2u(__floats2half2_rn(u.x, u.y));
    o.y = h2u(__floats2half2_rn(u.z, u.w));
    o.z = h2u(__floats2half2_rn(v.x, v.y));
    o.w = h2u(__floats2half2_rn(v.z, v.w));
    d[i] = o;
}

// ===========================================================================
// Fused projection GEMM (fp16 in, fp32 accum): C_z = A_z * W_z^T + bias_z
// Tile 128m x 64n x 64k, 3-stage cp.async, 8 warps (4m x 2n), ldmatrix frags.
// heads=1: head-split __half output; heads=0: row-major fp32 output.
// ===========================================================================
#define GBM 128
#define GBN 64
#define GBK 64
#define GKT (D_ / GBK)              // 8
#define GA(s) ((s) * 16384)         // A: 128 rows x 128B
#define GB(s) (49152 + (s) * 8192)  // W: 64 rows x 128B
#define GSM 73728

__global__ __launch_bounds__(256) void gemm3_kernel(
    const __half* __restrict__ A0, const __half* __restrict__ A1, const __half* __restrict__ A2,
    const __half* __restrict__ W0, const __half* __restrict__ W1, const __half* __restrict__ W2,
    const float* __restrict__ bp0, const float* __restrict__ bp1, const float* __restrict__ bp2,
    __half* __restrict__ Ch0, __half* __restrict__ Ch1, __half* __restrict__ Ch2,
    float* __restrict__ Cf, int heads)
{
    extern __shared__ char sm[];
    const uint32_t sb = smem_to_u32(sm);
    const int z = blockIdx.z;
    const __half* A    = (z == 0) ? A0 : (z == 1) ? A1 : A2;
    const __half* W    = (z == 0) ? W0 : (z == 1) ? W1 : W2;
    const float* bias  = (z == 0) ? bp0 : (z == 1) ? bp1 : bp2;
    __half* Ch         = (z == 0) ? Ch0 : (z == 1) ? Ch1 : Ch2;

    const int tid = threadIdx.x;
    const int lane = tid & 31, warp = tid >> 5;
    const int wm = warp >> 1, wn = warp & 1;
    const int g = lane >> 2, t = lane & 3;
    const int m0 = blockIdx.y * GBM, n0 = blockIdx.x * GBN;

    auto stage = [&](int kt, int s) {
        const __half* Ab = A + (size_t)m0 * D_ + kt * GBK;
#pragma unroll
        for (int i = 0; i < 4; ++i) {          // A: 128 rows x 8 chunks
            int ci = tid + 256 * i;
            int row = ci >> 3, ch = ci & 7;
            cp16(sb + GA(s) + row * 128 + ((ch ^ (row & 7)) << 4),
                 Ab + (size_t)row * D_ + ch * 8);
        }
        const __half* Wb = W + (size_t)n0 * D_ + kt * GBK;
#pragma unroll
        for (int i = 0; i < 2; ++i) {          // W: 64 rows x 8 chunks
            int ci = tid + 256 * i;
            int row = ci >> 3, ch = ci & 7;
            cp16(sb + GB(s) + row * 128 + ((ch ^ (row & 7)) << 4),
                 Wb + (size_t)row * D_ + ch * 8);
        }
        CP_COMMIT;
    };

    stage(0, 0);
    stage(1, 1);

    // per-lane ldmatrix geometry
    const int l7 = lane & 7;
    const int rowA = wm * 32 + l7 + ((lane >> 3) & 1) * 8;   // + mt*16
    const int kchA = lane >> 4;
    const int rowB = wn * 32 + l7 + (lane >> 4) * 8;         // + ntp*16
    const int kchB = (lane >> 3) & 1;

    float acc[2][4][4] = {};

#pragma unroll 1
    for (int kt = 0; kt < GKT; ++kt) {
        if (kt < GKT - 1) { CP_WAIT(1); } else { CP_WAIT(0); }
        __syncthreads();
        if (kt + 2 < GKT) stage(kt + 2, (kt + 2) % 3);

        const uint32_t Ao = sb + GA(kt % 3), Bo = sb + GB(kt % 3);
#pragma unroll
        for (int kk = 0; kk < 4; ++kk) {
            uint32_t a[2][4], b[2][4];
#pragma unroll
            for (int mt = 0; mt < 2; ++mt)
                ldsm4(a[mt], Ao + (uint32_t)(rowA + mt * 16) * 128
                             + (((2 * kk + kchA) ^ l7) << 4));
#pragma unroll
            for (int ntp = 0; ntp < 2; ++ntp)
                ldsm4(b[ntp], Bo + (uint32_t)(rowB + ntp * 16) * 128
                              + (((2 * kk + kchB) ^ l7) << 4));
#pragma unroll
            for (int mt = 0; mt < 2; ++mt)
#pragma unroll
                for (int nt = 0; nt < 4; ++nt)
                    mma_f16(acc[mt][nt], a[mt], &b[nt >> 1][(nt & 1) * 2]);
        }
    }

    // Epilogue
#pragma unroll
    for (int mt = 0; mt < 2; ++mt) {
#pragma unroll
        for (int nt = 0; nt < 4; ++nt) {
            int n = n0 + wn * 32 + nt * 8 + 2 * t;
            float2 bv = *(const float2*)&bias[n];
            float2 r0, r1;
            r0.x = acc[mt][nt][0] + bv.x; r0.y = acc[mt][nt][1] + bv.y;
            r1.x = acc[mt][nt][2] + bv.x; r1.y = acc[mt][nt][3] + bv.y;
            int m_a = m0 + wm * 32 + mt * 16 + g;
            int m_b = m_a + 8;
            if (heads) {
                int h = n >> 6, dk = n & 63;
                int ba = m_a >> 10, la = m_a & (L_ - 1);
                int bb = m_b >> 10, lb = m_b & (L_ - 1);
                *(__half2*)&Ch[((size_t)(ba * H_ + h) * L_ + la) * DK_ + dk] =
                    __floats2half2_rn(r0.x, r0.y);
                *(__half2*)&Ch[((size_t)(bb * H_ + h) * L_ + lb) * DK_ + dk] =
                    __floats2half2_rn(r1.x, r1.y);
            } else {
                *(float2*)&Cf[(size_t)m_a * D_ + n] = r0;
                *(float2*)&Cf[(size_t)m_b * D_ + n] = r1;
            }
        }
    }
}

// ===========================================================================
// Flash attention, fp16 mma m16n8k16 + ldmatrix, cp.async K(x2)/V(x3) bufs.
// CTA: one (b,h) x 64 q-rows; k-tile 64; 8 warps (4m x 2n). 3 barriers/tile.
// All tiles: 128B rows, 16B-chunk XOR swizzle.
// ===========================================================================
#define AQ 0
#define APof 8192
#define AK(s) (16384 + (s) * 8192)   // 2 bufs
#define AV(s) (32768 + (s) * 8192)   // 3 bufs
#define ARM 57344
#define ARS 57856
#define ASMs 58368

__global__ __launch_bounds__(256) void attn_kernel(
    const __half* __restrict__ Q, const __half* __restrict__ K,
    const __half* __restrict__ V, const float* __restrict__ dist,
    const unsigned char* __restrict__ mask,
    const float* __restrict__ logwb, __half* __restrict__ X)
{
    extern __shared__ char sm[];
    const uint32_t sb = smem_to_u32(sm);
    float* redm = (float*)(sm + ARM);
    float* reds = (float*)(sm + ARS);

    const int tid = threadIdx.x;
    const int lane = tid & 31, warp = tid >> 5;
    const int wm = warp >> 1, wn = warp & 1;
    const int g = lane >> 2, t = lane & 3;
    const int l7 = lane & 7;
    const int bh = blockIdx.y;
    const int b = bh >> 3, h = bh & 7;
    const int q0 = blockIdx.x * 64;
    const float wb = __expf(logwb[h]);
    const int qr = wm * 16;

    const __half* Qb = Q + (size_t)(bh * L_ + q0) * DK_;
    const __half* Kb = K + (size_t)bh * L_ * DK_;
    const __half* Vb = V + (size_t)bh * L_ * DK_;

    auto stageKV = [&](int tile, int kbuf, int vbuf) {
        const __half* Kt = Kb + (size_t)tile * 64 * DK_;
        const __half* Vt = Vb + (size_t)tile * 64 * DK_;
#pragma unroll
        for (int i = 0; i < 2; ++i) {
            int ci = tid + 256 * i;
            int row = ci >> 3, ch = ci & 7;
            cp16(sb + AK(kbuf) + row * 128 + ((ch ^ (row & 7)) << 4),
                 Kt + row * DK_ + ch * 8);
            cp16(sb + AV(vbuf) + row * 128 + ((ch ^ (row & 7)) << 4),
                 Vt + row * DK_ + ch * 8);
        }
        CP_COMMIT;
    };

    // Stage Q, then tiles 0 and 1
    {
#pragma unroll
        for (int i = 0; i < 2; ++i) {
            int ci = tid + 256 * i;
            int row = ci >> 3, ch = ci & 7;
            cp16(sb + AQ + row * 128 + ((ch ^ (row & 7)) << 4),
                 Qb + row * DK_ + ch * 8);
        }
        CP_COMMIT;
    }
    stageKV(0, 0, 0);
    stageKV(1, 1, 1);

    CP_WAIT(2);
    __syncthreads();

    // Q fragments (A operand, kept in regs whole loop)
    uint32_t qa[4][4];
#pragma unroll
    for (int kk = 0; kk < 4; ++kk)
        ldsm4(qa[kk], sb + AQ + (uint32_t)(qr + l7 + ((lane >> 3) & 1) * 8) * 128
                      + (((2 * kk + (lane >> 4)) ^ l7) << 4));

    float o[4][4] = {};
    float mrow0 = -1e30f, mrow1 = -1e30f;
    float lrow0 = 0.f, lrow1 = 0.f;

    const float* dro0 = dist + (size_t)(b * L_ + q0 + qr + g) * L_;
    const float* dro1 = dro0 + 8 * L_;
    const unsigned char* mro0 = mask + (size_t)(b * L_ + q0 + qr + g) * L_;
    const unsigned char* mro1 = mro0 + 8 * L_;

    // ldmatrix per-lane geometry
    const int keyB = wn * 32 + l7 + (lane >> 4) * 8;   // K frag (+ntp*16)
    const int kchB = (lane >> 3) & 1;
    const int rowP = qr + l7 + ((lane >> 3) & 1) * 8;  // P frag rows
    const int kchP = lane >> 4;
    const int keyV = l7 + ((lane >> 3) & 1) * 8;       // V frag (+kk*16)
    const int dchV = wn * 4 + (lane >> 4);             // (+ntp*2)

#pragma unroll 1
    for (int it = 0; it < 16; ++it) {
        const int k0 = it * 64;
        if (it < 15) { CP_WAIT(1); } else { CP_WAIT(0); }
        __syncthreads();                       // sync1: tile `it` staged
        const uint32_t Ko = sb + AK(it & 1), Vo = sb + AV(it % 3);

        // Prefetch dist/mask (overlaps QK^T)
        const int cb = k0 + wn * 32 + 2 * t;
        float2 dv0[4], dv1[4]; uchar2 mv0[4], mv1[4];
#pragma unroll
        for (int nt = 0; nt < 4; ++nt) {
            int c = cb + nt * 8;
            dv0[nt] = *(const float2*)&dro0[c];
            dv1[nt] = *(const float2*)&dro1[c];
            mv0[nt] = *(const uchar2*)&mro0[c];
            mv1[nt] = *(const uchar2*)&mro1[c];
        }

        // S = Q K^T
        float s[4][4] = {};
#pragma unroll
        for (int kk = 0; kk < 4; ++kk) {
            uint32_t kb[2][4];
#pragma unroll
            for (int ntp = 0; ntp < 2; ++ntp)
                ldsm4(kb[ntp], Ko + (uint32_t)(keyB + ntp * 16) * 128
                               + (((2 * kk + kchB) ^ l7) << 4));
#pragma unroll
            for (int nt = 0; nt < 4; ++nt)
                mma_f16(s[nt], qa[kk], &kb[nt >> 1][(nt & 1) * 2]);
        }

        // scale + distance bias + mask
#pragma unroll
        for (int nt = 0; nt < 4; ++nt) {
            s[nt][0] = mv0[nt].x ? -1e9f : s[nt][0] * 0.125f - dv0[nt].x * wb;
            s[nt][1] = mv0[nt].y ? -1e9f : s[nt][1] * 0.125f - dv0[nt].y * wb;
            s[nt][2] = mv1[nt].x ? -1e9f : s[nt][2] * 0.125f - dv1[nt].x * wb;
            s[nt][3] = mv1[nt].y ? -1e9f : s[nt][3] * 0.125f - dv1[nt].y * wb;
        }

        // row max
        float tm0 = -1e30f, tm1 = -1e30f;
#pragma unroll
        for (int nt = 0; nt < 4; ++nt) {
            tm0 = fmaxf(tm0, fmaxf(s[nt][0], s[nt][1]));
            tm1 = fmaxf(tm1, fmaxf(s[nt][2], s[nt][3]));
        }
        tm0 = fmaxf(tm0, __shfl_xor_sync(0xffffffff, tm0, 1));
        tm0 = fmaxf(tm0, __shfl_xor_sync(0xffffffff, tm0, 2));
        tm1 = fmaxf(tm1, __shfl_xor_sync(0xffffffff, tm1, 1));
        tm1 = fmaxf(tm1, __shfl_xor_sync(0xffffffff, tm1, 2));
        if (t == 0) {
            redm[wn * 64 + qr + g] = tm0;
            redm[wn * 64 + qr + g + 8] = tm1;
        }
        __syncthreads();                       // sync2: K reads + redm done

        // stage tile it+2 (K into buf it&1 just freed; V into 3rd buf)
        if (it + 2 < 16) stageKV(it + 2, it & 1, (it + 2) % 3);

        float mn0 = fmaxf(mrow0, fmaxf(redm[qr + g], redm[64 + qr + g]));
        float mn1 = fmaxf(mrow1, fmaxf(redm[qr + g + 8], redm[64 + qr + g + 8]));
        float sc0 = __expf(mrow0 - mn0);
        float sc1 = __expf(mrow1 - mn1);
        mrow0 = mn0; mrow1 = mn1;

        // P = exp(S - m) -> fp16 P tile, partial sums
        const uint32_t prow0 = sb + APof + (uint32_t)(qr + g) * 128;
        const uint32_t prow1 = prow0 + 8 * 128;
        float sum0 = 0.f, sum1 = 0.f;
#pragma unroll
        for (int nt = 0; nt < 4; ++nt) {
            int c = wn * 32 + nt * 8 + 2 * t;
            float p00 = __expf(s[nt][0] - mn0);
            float p01 = __expf(s[nt][1] - mn0);
            float p10 = __expf(s[nt][2] - mn1);
            float p11 = __expf(s[nt][3] - mn1);
            uint32_t off = ((((uint32_t)c >> 3) ^ (uint32_t)g) << 4) + (c & 7) * 2;
            __half2 hp0 = __floats2half2_rn(p00, p01);
            __half2 hp1 = __floats2half2_rn(p10, p11);
            asm volatile("st.shared.b32 [%0], %1;" :: "r"(prow0 + off), "r"(h2u(hp0)));
            asm volatile("st.shared.b32 [%0], %1;" :: "r"(prow1 + off), "r"(h2u(hp1)));
            sum0 += p00 + p01;
            sum1 += p10 + p11;
        }
        sum0 += __shfl_xor_sync(0xffffffff, sum0, 1);
        sum0 += __shfl_xor_sync(0xffffffff, sum0, 2);
        sum1 += __shfl_xor_sync(0xffffffff, sum1, 1);
        sum1 += __shfl_xor_sync(0xffffffff, sum1, 2);
        if (t == 0) {
            reds[wn * 64 + qr + g] = sum0;
            reds[wn * 64 + qr + g + 8] = sum1;
        }

        // rescale O
#pragma unroll
        for (int nt = 0; nt < 4; ++nt) {
            o[nt][0] *= sc0; o[nt][1] *= sc0;
            o[nt][2] *= sc1; o[nt][3] *= sc1;
        }
        __syncthreads();                       // sync3: P + reds visible

        lrow0 = lrow0 * sc0 + reds[qr + g] + reds[64 + qr + g];
        lrow1 = lrow1 * sc1 + reds[qr + g + 8] + reds[64 + qr + g + 8];

        // O += P V
#pragma unroll
        for (int kk = 0; kk < 4; ++kk) {
            uint32_t pa[4], vb[2][4];
            ldsm4(pa, sb + APof + (uint32_t)rowP * 128
                      + (((2 * kk + kchP) ^ l7) << 4));
#pragma unroll
            for (int ntp = 0; ntp < 2; ++ntp)
                ldsm4t(vb[ntp], Vo + (uint32_t)(kk * 16 + keyV) * 128
                                + (((dchV + ntp * 2) ^ l7) << 4));
#pragma unroll
            for (int nt = 0; nt < 4; ++nt)
                mma_f16(o[nt], pa, &vb[nt >> 1][(nt & 1) * 2]);
        }
        // no sync4: next P writes are after next sync2; staging targets free bufs
    }

    // Normalize, write X (fp16) in (B, L, D)
    float inv0 = 1.f / lrow0;
    float inv1 = 1.f / lrow1;
    const size_t xr0 = (size_t)(b * L_ + q0 + qr + g) * D_ + h * DK_;
    const size_t xr1 = xr0 + 8 * D_;
#pragma unroll
    for (int nt = 0; nt < 4; ++nt) {
        int c = wn * 32 + nt * 8 + 2 * t;
        *(__half2*)&X[xr0 + c] = __floats2half2_rn(o[nt][0] * inv0, o[nt][1] * inv0);
        *(__half2*)&X[xr1 + c] = __floats2half2_rn(o[nt][2] * inv1, o[nt][3] * inv1);
    }
}

// ---------------------------------------------------------------------------
extern "C" void kernel_launch(void* const* d_in, const int* in_sizes, int n_in,
                              void* d_out, int out_size)
{
    const float* query = (const float*)d_in[0];
    const float* key_  = (const float*)d_in[1];
    const float* value = (const float*)d_in[2];
    const float* dist  = (const float*)d_in[3];
    const unsigned char* mask = (const unsigned char*)d_in[4];
    const float* Wq = (const float*)d_in[5];
    const float* bq = (const float*)d_in[6];
    const float* Wk = (const float*)d_in[7];
    const float* bk = (const float*)d_in[8];
    const float* Wv = (const float*)d_in[9];
    const float* bv = (const float*)d_in[10];
    const float* Wo = (const float*)d_in[11];
    const float* bo = (const float*)d_in[12];
    const float* logwb = (const float*)d_in[13];

    __half *Ah, *Wh, *Qp, *Kp, *Vp, *Xp;
    cudaGetSymbolAddress((void**)&Ah, g_Ah);
    cudaGetSymbolAddress((void**)&Wh, g_Wh);
    cudaGetSymbolAddress((void**)&Qp, g_Q);
    cudaGetSymbolAddress((void**)&Kp, g_K);
    cudaGetSymbolAddress((void**)&Vp, g_V);
    cudaGetSymbolAddress((void**)&Xp, g_X);
    __half* A0 = Ah;            __half* A1 = Ah + (size_t)M_ * D_;
    __half* A2 = Ah + 2 * (size_t)M_ * D_;
    __half* W0 = Wh;            __half* W1 = Wh + (size_t)D_ * D_;
    __half* W2 = Wh + 2 * (size_t)D_ * D_;
    __half* W3 = Wh + 3 * (size_t)D_ * D_;

    cudaFuncSetAttribute(gemm3_kernel,
                         cudaFuncAttributeMaxDynamicSharedMemorySize, GSM);
    cudaFuncSetAttribute(attn_kernel,
                         cudaFuncAttributeMaxDynamicSharedMemorySize, ASMs);

    // fp32 -> fp16 conversion: inputs (3 x 4.19M elems), weights (4 x 262K)
    cvt_kernel<<<dim3(M_ * D_ / (8 * 256), 1, 3), 256>>>(
        (const float4*)query, (const float4*)key_, (const float4*)value,
        (const float4*)query,
        (uint4*)A0, (uint4*)A1, (uint4*)A2, (uint4*)A0);
    cvt_kernel<<<dim3(D_ * D_ / (8 * 256), 1, 4), 256>>>(
        (const float4*)Wq, (const float4*)Wk, (const float4*)Wv, (const float4*)Wo,
        (uint4*)W0, (uint4*)W1, (uint4*)W2, (uint4*)W3);

    // Fused Q/K/V projections
    gemm3_kernel<<<dim3(D_ / GBN, M_ / GBM, 3), 256, GSM>>>(
        A0, A1, A2, W0, W1, W2, bq, bk, bv, Qp, Kp, Vp, nullptr, 1);

    attn_kernel<<<dim3(L_ / 64, B_ * H_), 256, ASMs>>>(
        Qp, Kp, Vp, dist, mask, logwb, Xp);

    // Output projection (fp32 out)
    gemm3_kernel<<<dim3(D_ / GBN, M_ / GBM, 1), 256, GSM>>>(
        Xp, Xp, Xp, W3, W3, W3, bo, bo, bo,
        nullptr, nullptr, nullptr, (float*)d_out, 0);
}

// round 9
// speedup vs baseline: 6.3275x; 1.3150x over previous
#include <cuda_runtime.h>
#include <cuda_fp16.h>
#include <cstdint>

#define B_ 8
#define L_ 1024
#define D_ 512
#define H_ 8
#define DK_ 64
#define M_ (B_*L_)

// Scratch (no allocations allowed)
__device__ __half g_Ah[3][M_*D_];   // fp16 query/key/value
__device__ __half g_Wh[4][D_*D_];   // fp16 Wq,Wk,Wv,Wo
__device__ __half g_Q[B_*H_*L_*DK_];
__device__ __half g_K[B_*H_*L_*DK_];
__device__ __half g_V[B_*H_*L_*DK_];
__device__ __half g_X[M_*D_];
__device__ __half g_DM[B_*L_*L_];   // fp16 dist with mask folded in

// ---------------------------------------------------------------------------
// helpers
// ---------------------------------------------------------------------------
__device__ __forceinline__ uint32_t smem_to_u32(const void* p) {
    uint32_t a;
    asm("{ .reg .u64 t; cvta.to.shared.u64 t, %1; cvt.u32.u64 %0, t; }"
        : "=r"(a) : "l"(p));
    return a;
}
__device__ __forceinline__ void cp16(uint32_t dst, const void* src) {
    asm volatile("cp.async.cg.shared.global [%0], [%1], 16;"
                 :: "r"(dst), "l"(src));
}
#define CP_COMMIT asm volatile("cp.async.commit_group;")
#define CP_WAIT(n) asm volatile("cp.async.wait_group %0;" :: "n"(n))

__device__ __forceinline__ void ldsm4(uint32_t* r, uint32_t addr) {
    asm volatile("ldmatrix.sync.aligned.m8n8.x4.shared.b16 {%0,%1,%2,%3}, [%4];"
        : "=r"(r[0]), "=r"(r[1]), "=r"(r[2]), "=r"(r[3]) : "r"(addr));
}
__device__ __forceinline__ void ldsm4t(uint32_t* r, uint32_t addr) {
    asm volatile("ldmatrix.sync.aligned.m8n8.x4.trans.shared.b16 {%0,%1,%2,%3}, [%4];"
        : "=r"(r[0]), "=r"(r[1]), "=r"(r[2]), "=r"(r[3]) : "r"(addr));
}
__device__ __forceinline__ void mma_f16(float* c, const uint32_t* a, const uint32_t* b) {
    asm volatile(
        "mma.sync.aligned.m16n8k16.row.col.f32.f16.f16.f32 "
        "{%0,%1,%2,%3}, {%4,%5,%6,%7}, {%8,%9}, {%0,%1,%2,%3};"
        : "+f"(c[0]), "+f"(c[1]), "+f"(c[2]), "+f"(c[3])
        : "r"(a[0]), "r"(a[1]), "r"(a[2]), "r"(a[3]), "r"(b[0]), "r"(b[1]));
}
__device__ __forceinline__ uint32_t h2u(__half2 h) { return *(uint32_t*)&h; }
__device__ __forceinline__ float ex2(float x) {
    float r;
    asm("ex2.approx.f32 %0, %1;" : "=f"(r) : "f"(x));
    return r;
}
// shared-space 32-bit load (avoids generic/shared address mixing)
__device__ __forceinline__ uint32_t lds32(uint32_t addr) {
    uint32_t v;
    asm volatile("ld.shared.b32 %0, [%1];" : "=r"(v) : "r"(addr));
    return v;
}

// ===========================================================================
// fp32 -> fp16 convert pass (8 elems/thread)
// ===========================================================================
__global__ void cvt_kernel(const float4* __restrict__ s0, const float4* __restrict__ s1,
                           const float4* __restrict__ s2, const float4* __restrict__ s3,
                           uint4* d0, uint4* d1, uint4* d2, uint4* d3)
{
    const int z = blockIdx.z;
    const float4* s = (z == 0) ? s0 : (z == 1) ? s1 : (z == 2) ? s2 : s3;
    uint4* d = (z == 0) ? d0 : (z == 1) ? d1 : (z == 2) ? d2 : d3;
    const int i = blockIdx.x * blockDim.x + threadIdx.x;
    float4 u = s[2 * i], v = s[2 * i + 1];
    uint4 o;
    o.x = h2u(__floats2half2_rn(u.x, u.y));
    o.y = h2u(__floats2half2_rn(u.z, u.w));
    o.z = h2u(__floats2half2_rn(v.x, v.y));
    o.w = h2u(__floats2half2_rn(v.z, v.w));
    d[i] = o;
}

// dist + mask -> fp16 dmc (masked entries become 6e4, i.e. exp -> 0)
__global__ void cvtdist_kernel(const float4* __restrict__ dist,
                               const uchar4* __restrict__ mask,
                               uint4* __restrict__ out)
{
    const int i = blockIdx.x * blockDim.x + threadIdx.x;
    float4 a = dist[2 * i], b = dist[2 * i + 1];
    uchar4 ma = mask[2 * i], mb = mask[2 * i + 1];
    if (ma.x) a.x = 60000.f;
    if (ma.y) a.y = 60000.f;
    if (ma.z) a.z = 60000.f;
    if (ma.w) a.w = 60000.f;
    if (mb.x) b.x = 60000.f;
    if (mb.y) b.y = 60000.f;
    if (mb.z) b.z = 60000.f;
    if (mb.w) b.w = 60000.f;
    uint4 o;
    o.x = h2u(__floats2half2_rn(a.x, a.y));
    o.y = h2u(__floats2half2_rn(a.z, a.w));
    o.z = h2u(__floats2half2_rn(b.x, b.y));
    o.w = h2u(__floats2half2_rn(b.z, b.w));
    out[i] = o;
}

// ===========================================================================
// Fused projection GEMM (fp16 in, fp32 accum): C_z = A_z * W_z^T + bias_z
// Tile 128m x 64n x 64k, 3-stage cp.async, 8 warps (4m x 2n), ldmatrix frags.
// ===========================================================================
#define GBM 128
#define GBN 64
#define GBK 64
#define GKT (D_ / GBK)              // 8
#define GA(s) ((s) * 16384)         // A: 128 rows x 128B
#define GB(s) (49152 + (s) * 8192)  // W: 64 rows x 128B
#define GSM 73728

__global__ __launch_bounds__(256) void gemm3_kernel(
    const __half* __restrict__ A0, const __half* __restrict__ A1, const __half* __restrict__ A2,
    const __half* __restrict__ W0, const __half* __restrict__ W1, const __half* __restrict__ W2,
    const float* __restrict__ bp0, const float* __restrict__ bp1, const float* __restrict__ bp2,
    __half* __restrict__ Ch0, __half* __restrict__ Ch1, __half* __restrict__ Ch2,
    float* __restrict__ Cf, int heads)
{
    extern __shared__ char sm[];
    const uint32_t sb = smem_to_u32(sm);
    const int z = blockIdx.z;
    const __half* A    = (z == 0) ? A0 : (z == 1) ? A1 : A2;
    const __half* W    = (z == 0) ? W0 : (z == 1) ? W1 : W2;
    const float* bias  = (z == 0) ? bp0 : (z == 1) ? bp1 : bp2;
    __half* Ch         = (z == 0) ? Ch0 : (z == 1) ? Ch1 : Ch2;

    const int tid = threadIdx.x;
    const int lane = tid & 31, warp = tid >> 5;
    const int wm = warp >> 1, wn = warp & 1;
    const int g = lane >> 2, t = lane & 3;
    const int m0 = blockIdx.y * GBM, n0 = blockIdx.x * GBN;

    auto stage = [&](int kt, int s) {
        const __half* Ab = A + (size_t)m0 * D_ + kt * GBK;
#pragma unroll
        for (int i = 0; i < 4; ++i) {
            int ci = tid + 256 * i;
            int row = ci >> 3, ch = ci & 7;
            cp16(sb + GA(s) + row * 128 + ((ch ^ (row & 7)) << 4),
                 Ab + (size_t)row * D_ + ch * 8);
        }
        const __half* Wb = W + (size_t)n0 * D_ + kt * GBK;
#pragma unroll
        for (int i = 0; i < 2; ++i) {
            int ci = tid + 256 * i;
            int row = ci >> 3, ch = ci & 7;
            cp16(sb + GB(s) + row * 128 + ((ch ^ (row & 7)) << 4),
                 Wb + (size_t)row * D_ + ch * 8);
        }
        CP_COMMIT;
    };

    stage(0, 0);
    stage(1, 1);

    const int l7 = lane & 7;
    const int rowA = wm * 32 + l7 + ((lane >> 3) & 1) * 8;
    const int kchA = lane >> 4;
    const int rowB = wn * 32 + l7 + (lane >> 4) * 8;
    const int kchB = (lane >> 3) & 1;

    float acc[2][4][4] = {};

#pragma unroll 1
    for (int kt = 0; kt < GKT; ++kt) {
        if (kt < GKT - 1) { CP_WAIT(1); } else { CP_WAIT(0); }
        __syncthreads();
        if (kt + 2 < GKT) stage(kt + 2, (kt + 2) % 3);

        const uint32_t Ao = sb + GA(kt % 3), Bo = sb + GB(kt % 3);
#pragma unroll
        for (int kk = 0; kk < 4; ++kk) {
            uint32_t a[2][4], b[2][4];
#pragma unroll
            for (int mt = 0; mt < 2; ++mt)
                ldsm4(a[mt], Ao + (uint32_t)(rowA + mt * 16) * 128
                             + (((2 * kk + kchA) ^ l7) << 4));
#pragma unroll
            for (int ntp = 0; ntp < 2; ++ntp)
                ldsm4(b[ntp], Bo + (uint32_t)(rowB + ntp * 16) * 128
                              + (((2 * kk + kchB) ^ l7) << 4));
#pragma unroll
            for (int mt = 0; mt < 2; ++mt)
#pragma unroll
                for (int nt = 0; nt < 4; ++nt)
                    mma_f16(acc[mt][nt], a[mt], &b[nt >> 1][(nt & 1) * 2]);
        }
    }

    // Epilogue
#pragma unroll
    for (int mt = 0; mt < 2; ++mt) {
#pragma unroll
        for (int nt = 0; nt < 4; ++nt) {
            int n = n0 + wn * 32 + nt * 8 + 2 * t;
            float2 bv = *(const float2*)&bias[n];
            float2 r0, r1;
            r0.x = acc[mt][nt][0] + bv.x; r0.y = acc[mt][nt][1] + bv.y;
            r1.x = acc[mt][nt][2] + bv.x; r1.y = acc[mt][nt][3] + bv.y;
            int m_a = m0 + wm * 32 + mt * 16 + g;
            int m_b = m_a + 8;
            if (heads) {
                int h = n >> 6, dk = n & 63;
                int ba = m_a >> 10, la = m_a & (L_ - 1);
                int bb = m_b >> 10, lb = m_b & (L_ - 1);
                *(__half2*)&Ch[((size_t)(ba * H_ + h) * L_ + la) * DK_ + dk] =
                    __floats2half2_rn(r0.x, r0.y);
                *(__half2*)&Ch[((size_t)(bb * H_ + h) * L_ + lb) * DK_ + dk] =
                    __floats2half2_rn(r1.x, r1.y);
            } else {
                *(float2*)&Cf[(size_t)m_a * D_ + n] = r0;
                *(float2*)&Cf[(size_t)m_b * D_ + n] = r1;
            }
        }
    }
}

// ===========================================================================
// Flash attention, fp16 mma + ldmatrix, cp.async K(x2)/V(x3)/dmc(x2) bufs.
// Softmax in log2 domain (ex2.approx). No hot-loop LDG at all.
// CTA: one (b,h) x 64 q-rows; k-tile 64; 8 warps (4m x 2n); 3 barriers/tile.
// ===========================================================================
#define AQ 0
#define APof 8192
#define AK(s) (16384 + (s) * 8192)   // 2 bufs
#define AV(s) (32768 + (s) * 8192)   // 3 bufs
#define ADM(s) (57344 + (s) * 8192)  // 2 bufs (fp16 dmc tile 64x64)
#define ARM 73728
#define ARS 74240
#define ASMs 74752

__global__ __launch_bounds__(256) void attn_kernel(
    const __half* __restrict__ Q, const __half* __restrict__ K,
    const __half* __restrict__ V, const __half* __restrict__ dmc,
    const float* __restrict__ logwb, __half* __restrict__ X)
{
    extern __shared__ char sm[];
    const uint32_t sb = smem_to_u32(sm);
    float* redm = (float*)(sm + ARM);
    float* reds = (float*)(sm + ARS);

    const int tid = threadIdx.x;
    const int lane = tid & 31, warp = tid >> 5;
    const int wm = warp >> 1, wn = warp & 1;
    const int g = lane >> 2, t = lane & 3;
    const int l7 = lane & 7;
    const int bh = blockIdx.y;
    const int b = bh >> 3, h = bh & 7;
    const int q0 = blockIdx.x * 64;
    const float LOG2E = 1.4426950408889634f;
    const float wb2 = __expf(logwb[h]) * LOG2E;   // bias scale, log2 domain
    const float c1 = 0.125f * LOG2E;              // qk scale, log2 domain
    const int qr = wm * 16;

    const __half* Qb = Q + (size_t)(bh * L_ + q0) * DK_;
    const __half* Kb = K + (size_t)bh * L_ * DK_;
    const __half* Vb = V + (size_t)bh * L_ * DK_;
    const __half* Db = dmc + (size_t)b * L_ * L_ + (size_t)q0 * L_;

    auto stageKVD = [&](int tile, int kbuf, int vbuf, int dbuf) {
        const __half* Kt = Kb + (size_t)tile * 64 * DK_;
        const __half* Vt = Vb + (size_t)tile * 64 * DK_;
        const __half* Dt = Db + tile * 64;
#pragma unroll
        for (int i = 0; i < 2; ++i) {
            int ci = tid + 256 * i;
            int row = ci >> 3, ch = ci & 7;
            uint32_t off = row * 128 + ((ch ^ (row & 7)) << 4);
            cp16(sb + AK(kbuf) + off, Kt + row * DK_ + ch * 8);
            cp16(sb + AV(vbuf) + off, Vt + row * DK_ + ch * 8);
            cp16(sb + ADM(dbuf) + off, Dt + (size_t)row * L_ + ch * 8);
        }
        CP_COMMIT;
    };

    // Stage Q, then tiles 0 and 1
    {
#pragma unroll
        for (int i = 0; i < 2; ++i) {
            int ci = tid + 256 * i;
            int row = ci >> 3, ch = ci & 7;
            cp16(sb + AQ + row * 128 + ((ch ^ (row & 7)) << 4),
                 Qb + row * DK_ + ch * 8);
        }
        CP_COMMIT;
    }
    stageKVD(0, 0, 0, 0);
    stageKVD(1, 1, 1, 1);

    CP_WAIT(2);
    __syncthreads();

    // Q fragments (kept in regs whole loop)
    uint32_t qa[4][4];
#pragma unroll
    for (int kk = 0; kk < 4; ++kk)
        ldsm4(qa[kk], sb + AQ + (uint32_t)(qr + l7 + ((lane >> 3) & 1) * 8) * 128
                      + (((2 * kk + (lane >> 4)) ^ l7) << 4));

    float o[4][4] = {};
    float mrow0 = -1e30f, mrow1 = -1e30f;
    float lrow0 = 0.f, lrow1 = 0.f;

    // ldmatrix / LDS per-lane geometry
    const int keyB = wn * 32 + l7 + (lane >> 4) * 8;
    const int kchB = (lane >> 3) & 1;
    const int rowP = qr + l7 + ((lane >> 3) & 1) * 8;
    const int kchP = lane >> 4;
    const int keyV = l7 + ((lane >> 3) & 1) * 8;
    const int dchV = wn * 4 + (lane >> 4);
    // dmc LDS offsets (shared-space): row qr+g (and +8), chunk (4wn+nt)^g, byte 4t
    const uint32_t dmr0 = (uint32_t)(qr + g) * 128 + 4 * t;
    const uint32_t dmr1 = dmr0 + 8 * 128;

#pragma unroll 1
    for (int it = 0; it < 16; ++it) {
        if (it < 15) { CP_WAIT(1); } else { CP_WAIT(0); }
        __syncthreads();                       // sync1: tile `it` staged
        const uint32_t Ko = sb + AK(it & 1), Vo = sb + AV(it % 3);
        const uint32_t Do = sb + ADM(it & 1);

        // S = Q K^T
        float s[4][4] = {};
#pragma unroll
        for (int kk = 0; kk < 4; ++kk) {
            uint32_t kb[2][4];
#pragma unroll
            for (int ntp = 0; ntp < 2; ++ntp)
                ldsm4(kb[ntp], Ko + (uint32_t)(keyB + ntp * 16) * 128
                               + (((2 * kk + kchB) ^ l7) << 4));
#pragma unroll
            for (int nt = 0; nt < 4; ++nt)
                mma_f16(s[nt], qa[kk], &kb[nt >> 1][(nt & 1) * 2]);
        }

        // bias from smem dmc tile: s2 = qk*c1 - d*wb2  (log2 domain)
        // NOTE: ld.shared on shared-space address (Do is sb-based!)
#pragma unroll
        for (int nt = 0; nt < 4; ++nt) {
            uint32_t co = (uint32_t)(((4 * wn + nt) ^ g) << 4);
            uint32_t du0 = lds32(Do + dmr0 + co);
            uint32_t du1 = lds32(Do + dmr1 + co);
            float2 d0 = __half22float2(*(__half2*)&du0);
            float2 d1 = __half22float2(*(__half2*)&du1);
            s[nt][0] = fmaf(s[nt][0], c1, -d0.x * wb2);
            s[nt][1] = fmaf(s[nt][1], c1, -d0.y * wb2);
            s[nt][2] = fmaf(s[nt][2], c1, -d1.x * wb2);
            s[nt][3] = fmaf(s[nt][3], c1, -d1.y * wb2);
        }

        // row max
        float tm0 = -1e30f, tm1 = -1e30f;
#pragma unroll
        for (int nt = 0; nt < 4; ++nt) {
            tm0 = fmaxf(tm0, fmaxf(s[nt][0], s[nt][1]));
            tm1 = fmaxf(tm1, fmaxf(s[nt][2], s[nt][3]));
        }
        tm0 = fmaxf(tm0, __shfl_xor_sync(0xffffffff, tm0, 1));
        tm0 = fmaxf(tm0, __shfl_xor_sync(0xffffffff, tm0, 2));
        tm1 = fmaxf(tm1, __shfl_xor_sync(0xffffffff, tm1, 1));
        tm1 = fmaxf(tm1, __shfl_xor_sync(0xffffffff, tm1, 2));
        if (t == 0) {
            redm[wn * 64 + qr + g] = tm0;
            redm[wn * 64 + qr + g + 8] = tm1;
        }
        __syncthreads();                       // sync2: K/dmc reads + redm done

        // stage tile it+2 into freed buffers
        if (it + 2 < 16) stageKVD(it + 2, it & 1, (it + 2) % 3, it & 1);

        float mn0 = fmaxf(mrow0, fmaxf(redm[qr + g], redm[64 + qr + g]));
        float mn1 = fmaxf(mrow1, fmaxf(redm[qr + g + 8], redm[64 + qr + g + 8]));
        float sc0 = ex2(mrow0 - mn0);
        float sc1 = ex2(mrow1 - mn1);
        mrow0 = mn0; mrow1 = mn1;

        // P = ex2(s - m) -> fp16 P tile, partial sums
        const uint32_t prow0 = sb + APof + (uint32_t)(qr + g) * 128;
        const uint32_t prow1 = prow0 + 8 * 128;
        float sum0 = 0.f, sum1 = 0.f;
#pragma unroll
        for (int nt = 0; nt < 4; ++nt) {
            int c = wn * 32 + nt * 8 + 2 * t;
            float p00 = ex2(s[nt][0] - mn0);
            float p01 = ex2(s[nt][1] - mn0);
            float p10 = ex2(s[nt][2] - mn1);
            float p11 = ex2(s[nt][3] - mn1);
            uint32_t off = ((((uint32_t)c >> 3) ^ (uint32_t)g) << 4) + (c & 7) * 2;
            __half2 hp0 = __floats2half2_rn(p00, p01);
            __half2 hp1 = __floats2half2_rn(p10, p11);
            asm volatile("st.shared.b32 [%0], %1;" :: "r"(prow0 + off), "r"(h2u(hp0)));
            asm volatile("st.shared.b32 [%0], %1;" :: "r"(prow1 + off), "r"(h2u(hp1)));
            sum0 += p00 + p01;
            sum1 += p10 + p11;
        }
        sum0 += __shfl_xor_sync(0xffffffff, sum0, 1);
        sum0 += __shfl_xor_sync(0xffffffff, sum0, 2);
        sum1 += __shfl_xor_sync(0xffffffff, sum1, 1);
        sum1 += __shfl_xor_sync(0xffffffff, sum1, 2);
        if (t == 0) {
            reds[wn * 64 + qr + g] = sum0;
            reds[wn * 64 + qr + g + 8] = sum1;
        }

        // rescale O
#pragma unroll
        for (int nt = 0; nt < 4; ++nt) {
            o[nt][0] *= sc0; o[nt][1] *= sc0;
            o[nt][2] *= sc1; o[nt][3] *= sc1;
        }
        __syncthreads();                       // sync3: P + reds visible

        lrow0 = lrow0 * sc0 + reds[qr + g] + reds[64 + qr + g];
        lrow1 = lrow1 * sc1 + reds[qr + g + 8] + reds[64 + qr + g + 8];

        // O += P V
#pragma unroll
        for (int kk = 0; kk < 4; ++kk) {
            uint32_t pa[4], vb[2][4];
            ldsm4(pa, sb + APof + (uint32_t)rowP * 128
                      + (((2 * kk + kchP) ^ l7) << 4));
#pragma unroll
            for (int ntp = 0; ntp < 2; ++ntp)
                ldsm4t(vb[ntp], Vo + (uint32_t)(kk * 16 + keyV) * 128
                                + (((dchV + ntp * 2) ^ l7) << 4));
#pragma unroll
            for (int nt = 0; nt < 4; ++nt)
                mma_f16(o[nt], pa, &vb[nt >> 1][(nt & 1) * 2]);
        }
    }

    // Normalize, write X (fp16) in (B, L, D)
    float inv0 = 1.f / lrow0;
    float inv1 = 1.f / lrow1;
    const size_t xr0 = (size_t)(b * L_ + q0 + qr + g) * D_ + h * DK_;
    const size_t xr1 = xr0 + 8 * D_;
#pragma unroll
    for (int nt = 0; nt < 4; ++nt) {
        int c = wn * 32 + nt * 8 + 2 * t;
        *(__half2*)&X[xr0 + c] = __floats2half2_rn(o[nt][0] * inv0, o[nt][1] * inv0);
        *(__half2*)&X[xr1 + c] = __floats2half2_rn(o[nt][2] * inv1, o[nt][3] * inv1);
    }
}

// ---------------------------------------------------------------------------
extern "C" void kernel_launch(void* const* d_in, const int* in_sizes, int n_in,
                              void* d_out, int out_size)
{
    const float* query = (const float*)d_in[0];
    const float* key_  = (const float*)d_in[1];
    const float* value = (const float*)d_in[2];
    const float* dist  = (const float*)d_in[3];
    const unsigned char* mask = (const unsigned char*)d_in[4];
    const float* Wq = (const float*)d_in[5];
    const float* bq = (const float*)d_in[6];
    const float* Wk = (const float*)d_in[7];
    const float* bk = (const float*)d_in[8];
    const float* Wv = (const float*)d_in[9];
    const float* bv = (const float*)d_in[10];
    const float* Wo = (const float*)d_in[11];
    const float* bo = (const float*)d_in[12];
    const float* logwb = (const float*)d_in[13];

    __half *Ah, *Wh, *Qp, *Kp, *Vp, *Xp, *Dp;
    cudaGetSymbolAddress((void**)&Ah, g_Ah);
    cudaGetSymbolAddress((void**)&Wh, g_Wh);
    cudaGetSymbolAddress((void**)&Qp, g_Q);
    cudaGetSymbolAddress((void**)&Kp, g_K);
    cudaGetSymbolAddress((void**)&Vp, g_V);
    cudaGetSymbolAddress((void**)&Xp, g_X);
    cudaGetSymbolAddress((void**)&Dp, g_DM);
    __half* A0 = Ah;            __half* A1 = Ah + (size_t)M_ * D_;
    __half* A2 = Ah + 2 * (size_t)M_ * D_;
    __half* W0 = Wh;            __half* W1 = Wh + (size_t)D_ * D_;
    __half* W2 = Wh + 2 * (size_t)D_ * D_;
    __half* W3 = Wh + 3 * (size_t)D_ * D_;

    cudaFuncSetAttribute(gemm3_kernel,
                         cudaFuncAttributeMaxDynamicSharedMemorySize, GSM);
    cudaFuncSetAttribute(attn_kernel,
                         cudaFuncAttributeMaxDynamicSharedMemorySize, ASMs);

    // fp32 -> fp16 conversion passes
    cvt_kernel<<<dim3(M_ * D_ / (8 * 256), 1, 3), 256>>>(
        (const float4*)query, (const float4*)key_, (const float4*)value,
        (const float4*)query,
        (uint4*)A0, (uint4*)A1, (uint4*)A2, (uint4*)A0);
    cvt_kernel<<<dim3(D_ * D_ / (8 * 256), 1, 4), 256>>>(
        (const float4*)Wq, (const float4*)Wk, (const float4*)Wv, (const float4*)Wo,
        (uint4*)W0, (uint4*)W1, (uint4*)W2, (uint4*)W3);
    cvtdist_kernel<<<B_ * L_ * L_ / (8 * 256), 256>>>(
        (const float4*)dist, (const uchar4*)mask, (uint4*)Dp);

    // Fused Q/K/V projections
    gemm3_kernel<<<dim3(D_ / GBN, M_ / GBM, 3), 256, GSM>>>(
        A0, A1, A2, W0, W1, W2, bq, bk, bv, Qp, Kp, Vp, nullptr, 1);

    attn_kernel<<<dim3(L_ / 64, B_ * H_), 256, ASMs>>>(
        Qp, Kp, Vp, Dp, logwb, Xp);

    // Output projection (fp32 out)
    gemm3_kernel<<<dim3(D_ / GBN, M_ / GBM, 1), 256, GSM>>>(
        Xp, Xp, Xp, W3, W3, W3, bo, bo, bo,
        nullptr, nullptr, nullptr, (float*)d_out, 0);
}